// round 2
// baseline (speedup 1.0000x reference)
#include <cuda_runtime.h>

#define BB 2
#define SS 2048
#define DD 1024
#define HH 16
#define HD 64

// Scratch for head-split projections: [B,H,S,64] each, 16MB x3 static.
__device__ float g_Q[BB*HH*SS*HD];
__device__ float g_K[BB*HH*SS*HD];
__device__ float g_V[BB*HH*SS*HD];

// ---------------------------------------------------------------------------
// Projection: y[i][j] = sum_k X[i][k] * W[j][k] + bias[j]
// M=4096, N=1024, K=1024. 128x128 block, BK=8, 256 threads, 8x8 micro-tile.
// Writes into head-split layout dst[((b*H+h)*S + s)*64 + d].
// ---------------------------------------------------------------------------
__global__ void __launch_bounds__(256) proj_kernel(const float* __restrict__ X,
                                                   const float* __restrict__ W,
                                                   const float* __restrict__ bias,
                                                   int which)
{
    float* dst = (which == 0) ? g_Q : ((which == 1) ? g_K : g_V);

    __shared__ float As[8][128];
    __shared__ float Bs[8][128];

    const int bi = blockIdx.y * 128;
    const int bj = blockIdx.x * 128;
    const int tid = threadIdx.x;
    const int tx = tid & 15;        // 16 col-groups
    const int ty = tid >> 4;        // 16 row-groups
    const int lr = tid >> 1;        // 0..127 (load row)
    const int lc = (tid & 1) * 4;   // 0 or 4 (load k offset)

    const float* Xp = X + (size_t)(bi + lr) * DD + lc;
    const float* Wp = W + (size_t)(bj + lr) * DD + lc;

    float acc[8][8];
#pragma unroll
    for (int i = 0; i < 8; i++)
#pragma unroll
        for (int j = 0; j < 8; j++) acc[i][j] = 0.0f;

    for (int k0 = 0; k0 < DD; k0 += 8) {
        float4 a4 = *(const float4*)(Xp + k0);
        float4 w4 = *(const float4*)(Wp + k0);
        As[lc + 0][lr] = a4.x; As[lc + 1][lr] = a4.y;
        As[lc + 2][lr] = a4.z; As[lc + 3][lr] = a4.w;
        Bs[lc + 0][lr] = w4.x; Bs[lc + 1][lr] = w4.y;
        Bs[lc + 2][lr] = w4.z; Bs[lc + 3][lr] = w4.w;
        __syncthreads();

#pragma unroll
        for (int k = 0; k < 8; k++) {
            float a[8], bb[8];
            *(float4*)&a[0]  = *(const float4*)&As[k][ty * 8];
            *(float4*)&a[4]  = *(const float4*)&As[k][ty * 8 + 4];
            *(float4*)&bb[0] = *(const float4*)&Bs[k][tx * 8];
            *(float4*)&bb[4] = *(const float4*)&Bs[k][tx * 8 + 4];
#pragma unroll
            for (int i = 0; i < 8; i++)
#pragma unroll
                for (int j = 0; j < 8; j++)
                    acc[i][j] = fmaf(a[i], bb[j], acc[i][j]);
        }
        __syncthreads();
    }

    // Epilogue: add bias, scatter into head-split layout.
#pragma unroll
    for (int ii = 0; ii < 8; ii++) {
        const int i = bi + ty * 8 + ii;
        const int b = i >> 11;          // i / S
        const int s = i & 2047;         // i % S
#pragma unroll
        for (int jj = 0; jj < 8; jj++) {
            const int j = bj + tx * 8 + jj;
            const int h = j >> 6;
            const int d = j & 63;
            dst[(((size_t)(b * HH + h)) * SS + s) * HD + d] = acc[ii][jj] + bias[j];
        }
    }
}

// ---------------------------------------------------------------------------
// Fused attention per (b, h, 16-row q-block). 512 threads (16 warps).
//   Phase 1: scores[16][2048] = 1/(8 * Q Kt) in 256-col chunks, 4x2 microtile.
//   Phase 2: softmax, one warp per row.
//   Phase 3: attn_mean += attn/H via red.global.add.v4.f32.
//   Phase 4: out = attn @ V, 8-way k-split; reduction reuses kv buffer.
// SMEM: sc 16x2048 (128KB) | kv 17408 f (K^T [64][256] / V [256][68] / red) |
//       qt [64][16]   => 51200 floats = 200KB dynamic.
// ---------------------------------------------------------------------------
#define SMEM_FLOATS (32768 + 17408 + 1024)
#define SMEM_BYTES  (SMEM_FLOATS * 4)

__global__ void __launch_bounds__(512) attn_kernel(float* __restrict__ out)
{
    extern __shared__ float sm[];
    float* sc  = sm;                      // scores / attn, [16][2048]
    float* kv  = sm + 32768;              // K^T [64][256] / V [256][68] / red
    float* qt  = sm + 32768 + 17408;      // Q^T [64][16]

    const int cta = blockIdx.x;           // b*2048 + h*128 + qb
    const int qb  = cta & 127;
    const int h   = (cta >> 7) & 15;
    const int b   = cta >> 11;
    const int q0  = qb * 16;
    const int tid = threadIdx.x;

    const float* Qg = g_Q + ((size_t)(b * HH + h) * SS + q0) * HD;
    const float* Kg = g_K + (size_t)(b * HH + h) * SS * HD;
    const float* Vg = g_V + (size_t)(b * HH + h) * SS * HD;

    // Load Q tile transposed: qt[d][r]  (first 256 threads)
    if (tid < 256) {
        const int r  = tid >> 4;
        const int c4 = (tid & 15) * 4;
        float4 v = *(const float4*)&Qg[r * HD + c4];
        qt[(c4 + 0) * 16 + r] = v.x;
        qt[(c4 + 1) * 16 + r] = v.y;
        qt[(c4 + 2) * 16 + r] = v.z;
        qt[(c4 + 3) * 16 + r] = v.w;
    }

    // ---- Phase 1: scores = 1 / (8 * Q K^T) ----
    const int rg = tid >> 7;          // 0..3 -> q rows rg*4..rg*4+3
    const int cg = tid & 127;         // 0..127 -> k cols cg*2..cg*2+1
    const int r0 = rg * 4;
    const int lrow  = tid & 255;      // load row within chunk
    const int lhalf = (tid >> 8) * 32;// d-offset half

    for (int kc = 0; kc < 8; kc++) {
        // Load 256 K rows, transposed: kv[d][kk]. Each thread: one half-row.
        const float* Krow = Kg + (size_t)(kc * 256 + lrow) * HD + lhalf;
#pragma unroll
        for (int d4 = 0; d4 < 8; d4++) {
            float4 v = *(const float4*)&Krow[d4 * 4];
            const int d = lhalf + d4 * 4;
            kv[(d + 0) * 256 + lrow] = v.x;
            kv[(d + 1) * 256 + lrow] = v.y;
            kv[(d + 2) * 256 + lrow] = v.z;
            kv[(d + 3) * 256 + lrow] = v.w;
        }
        __syncthreads();

        float acc[4][2];
#pragma unroll
        for (int i = 0; i < 4; i++) { acc[i][0] = 0.0f; acc[i][1] = 0.0f; }

#pragma unroll 8
        for (int d = 0; d < 64; d++) {
            float qv[4], kvv[2];
            *(float4*)qv  = *(const float4*)&qt[d * 16 + r0];   // warp-broadcast
            *(float2*)kvv = *(const float2*)&kv[d * 256 + cg * 2];
#pragma unroll
            for (int i = 0; i < 4; i++) {
                acc[i][0] = fmaf(qv[i], kvv[0], acc[i][0]);
                acc[i][1] = fmaf(qv[i], kvv[1], acc[i][1]);
            }
        }

#pragma unroll
        for (int i = 0; i < 4; i++) {
            float2 sv;
            sv.x = __fdividef(1.0f, 8.0f * acc[i][0]);
            sv.y = __fdividef(1.0f, 8.0f * acc[i][1]);
            *(float2*)&sc[(r0 + i) * 2048 + kc * 256 + cg * 2] = sv;
        }
        __syncthreads();  // kv reuse guard
    }

    // ---- Phase 2: softmax per row (one warp per row) ----
    {
        const int warp = tid >> 5;    // 0..15 == row
        const int lane = tid & 31;
        float* row = sc + warp * 2048;
        float m = -3.4e38f;
        for (int k = lane; k < 2048; k += 32) m = fmaxf(m, row[k]);
#pragma unroll
        for (int o = 16; o; o >>= 1) m = fmaxf(m, __shfl_xor_sync(0xffffffffu, m, o));
        float ssum = 0.0f;
        for (int k = lane; k < 2048; k += 32) {
            float e = __expf(row[k] - m);
            row[k] = e;
            ssum += e;
        }
#pragma unroll
        for (int o = 16; o; o >>= 1) ssum += __shfl_xor_sync(0xffffffffu, ssum, o);
        const float inv = __fdividef(1.0f, ssum);
        for (int k = lane; k < 2048; k += 32) row[k] *= inv;
    }
    __syncthreads();

    // ---- Phase 3: attn_mean += attn / H  (vectorized global reduction) ----
    {
        float* am = out + (size_t)BB * SS * DD;
        for (int idx4 = tid; idx4 < 8192; idx4 += 512) {
            const int rr = idx4 >> 9;             // row 0..15
            const int kk = (idx4 & 511) * 4;      // col (x4)
            float4 v = *(const float4*)&sc[rr * 2048 + kk];
            v.x *= 0.0625f; v.y *= 0.0625f; v.z *= 0.0625f; v.w *= 0.0625f;
            float* p = &am[((size_t)(b * SS + q0 + rr)) * SS + kk];
            asm volatile("red.global.add.v4.f32 [%0], {%1, %2, %3, %4};"
                         :: "l"(p), "f"(v.x), "f"(v.y), "f"(v.z), "f"(v.w)
                         : "memory");
        }
    }

    // ---- Phase 4: out = attn @ V ----
    {
        const int dg  = tid & 15;          // 16 d-groups of 4
        const int rgq = (tid >> 4) & 3;    // 4 row-groups of 4
        const int kg  = tid >> 6;          // 8 k-split groups
        const int rr0 = rgq * 4;

        float acc2[4][4];
#pragma unroll
        for (int i = 0; i < 4; i++)
#pragma unroll
            for (int j = 0; j < 4; j++) acc2[i][j] = 0.0f;

        for (int vc = 0; vc < 8; vc++) {
            // Load V chunk [256][64] with row pad 68 (bank-conflict-free).
            const float* Vrow = Vg + (size_t)(vc * 256 + lrow) * HD + lhalf;
#pragma unroll
            for (int d4 = 0; d4 < 8; d4++) {
                float4 v = *(const float4*)&Vrow[d4 * 4];
                *(float4*)&kv[lrow * 68 + lhalf + d4 * 4] = v;
            }
            __syncthreads();

            const float* scb = sc + vc * 256;
#pragma unroll 4
            for (int kk2 = 0; kk2 < 32; kk2++) {
                const int k = kg * 32 + kk2;
                float vv[4];
                *(float4*)vv = *(const float4*)&kv[k * 68 + dg * 4];
                float a0 = scb[(rr0 + 0) * 2048 + k];
                float a1 = scb[(rr0 + 1) * 2048 + k];
                float a2 = scb[(rr0 + 2) * 2048 + k];
                float a3 = scb[(rr0 + 3) * 2048 + k];
#pragma unroll
                for (int j = 0; j < 4; j++) {
                    acc2[0][j] = fmaf(a0, vv[j], acc2[0][j]);
                    acc2[1][j] = fmaf(a1, vv[j], acc2[1][j]);
                    acc2[2][j] = fmaf(a2, vv[j], acc2[2][j]);
                    acc2[3][j] = fmaf(a3, vv[j], acc2[3][j]);
                }
            }
            __syncthreads();
        }

        // Cross-kg reduction: reuse kv buffer (8 groups x 16 rows x 64 cols).
        float* red = kv;
#pragma unroll
        for (int i = 0; i < 4; i++) {
            float4 v = make_float4(acc2[i][0], acc2[i][1], acc2[i][2], acc2[i][3]);
            *(float4*)&red[(kg * 16 + rr0 + i) * 64 + dg * 4] = v;
        }
        __syncthreads();

        for (int e = tid; e < 16 * 64; e += 512) {
            const int r = e >> 6;
            const int d = e & 63;
            float v = 0.0f;
#pragma unroll
            for (int g = 0; g < 8; g++) v += red[(g * 16 + r) * 64 + d];
            out[((size_t)(b * SS + q0 + r)) * DD + h * HD + d] = v;
        }
    }
}

// ---------------------------------------------------------------------------
extern "C" void kernel_launch(void* const* d_in, const int* in_sizes, int n_in,
                              void* d_out, int out_size)
{
    const float* query = (const float*)d_in[0];
    const float* key_  = (const float*)d_in[1];
    const float* value = (const float*)d_in[2];
    const float* Wq    = (const float*)d_in[3];
    const float* bq    = (const float*)d_in[4];
    const float* Wk    = (const float*)d_in[5];
    const float* bk    = (const float*)d_in[6];
    const float* Wv    = (const float*)d_in[7];
    const float* bv    = (const float*)d_in[8];
    float* out = (float*)d_out;

    // Zero the attn_mean accumulation region (after the [B,S,D] out block).
    cudaMemsetAsync(out + (size_t)BB * SS * DD, 0,
                    (size_t)BB * SS * SS * sizeof(float));

    dim3 pg(DD / 128, (BB * SS) / 128);
    proj_kernel<<<pg, 256>>>(query, Wq, bq, 0);
    proj_kernel<<<pg, 256>>>(key_,  Wk, bk, 1);
    proj_kernel<<<pg, 256>>>(value, Wv, bv, 2);

    cudaFuncSetAttribute(attn_kernel,
                         cudaFuncAttributeMaxDynamicSharedMemorySize, SMEM_BYTES);
    attn_kernel<<<BB * HH * (SS / 16), 512, SMEM_BYTES>>>(out);
}

// round 4
// speedup vs baseline: 1.4672x; 1.4672x over previous
#include <cuda_runtime.h>
#include <cstdint>

#define BB 2
#define SS 2048
#define DD 1024
#define HH 16
#define HD 64

// Scratch for head-split projections: [B,H,S,64] each, 16MB x3 static.
__device__ float g_Q[BB*HH*SS*HD];
__device__ float g_K[BB*HH*SS*HD];
__device__ float g_V[BB*HH*SS*HD];

// ---------------------------------------------------------------------------
// Projection: y[i][j] = sum_k X[i][k] * W[j][k] + bias[j]
// M=4096, N=1024, K=1024. 128x128 block, BK=8, 256 threads, 8x8 micro-tile.
// Writes into head-split layout dst[((b*H+h)*S + s)*64 + d].
// ---------------------------------------------------------------------------
__global__ void __launch_bounds__(256) proj_kernel(const float* __restrict__ X,
                                                   const float* __restrict__ W,
                                                   const float* __restrict__ bias,
                                                   int which)
{
    float* dst = (which == 0) ? g_Q : ((which == 1) ? g_K : g_V);

    __shared__ float As[8][128];
    __shared__ float Bs[8][128];

    const int bi = blockIdx.y * 128;
    const int bj = blockIdx.x * 128;
    const int tid = threadIdx.x;
    const int tx = tid & 15;        // 16 col-groups
    const int ty = tid >> 4;        // 16 row-groups
    const int lr = tid >> 1;        // 0..127 (load row)
    const int lc = (tid & 1) * 4;   // 0 or 4 (load k offset)

    const float* Xp = X + (size_t)(bi + lr) * DD + lc;
    const float* Wp = W + (size_t)(bj + lr) * DD + lc;

    float acc[8][8];
#pragma unroll
    for (int i = 0; i < 8; i++)
#pragma unroll
        for (int j = 0; j < 8; j++) acc[i][j] = 0.0f;

    for (int k0 = 0; k0 < DD; k0 += 8) {
        float4 a4 = *(const float4*)(Xp + k0);
        float4 w4 = *(const float4*)(Wp + k0);
        As[lc + 0][lr] = a4.x; As[lc + 1][lr] = a4.y;
        As[lc + 2][lr] = a4.z; As[lc + 3][lr] = a4.w;
        Bs[lc + 0][lr] = w4.x; Bs[lc + 1][lr] = w4.y;
        Bs[lc + 2][lr] = w4.z; Bs[lc + 3][lr] = w4.w;
        __syncthreads();

#pragma unroll
        for (int k = 0; k < 8; k++) {
            float a[8], bb[8];
            *(float4*)&a[0]  = *(const float4*)&As[k][ty * 8];
            *(float4*)&a[4]  = *(const float4*)&As[k][ty * 8 + 4];
            *(float4*)&bb[0] = *(const float4*)&Bs[k][tx * 8];
            *(float4*)&bb[4] = *(const float4*)&Bs[k][tx * 8 + 4];
#pragma unroll
            for (int i = 0; i < 8; i++)
#pragma unroll
                for (int j = 0; j < 8; j++)
                    acc[i][j] = fmaf(a[i], bb[j], acc[i][j]);
        }
        __syncthreads();
    }

    // Epilogue: add bias, scatter into head-split layout.
#pragma unroll
    for (int ii = 0; ii < 8; ii++) {
        const int i = bi + ty * 8 + ii;
        const int b = i >> 11;          // i / S
        const int s = i & 2047;         // i % S
#pragma unroll
        for (int jj = 0; jj < 8; jj++) {
            const int j = bj + tx * 8 + jj;
            const int h = j >> 6;
            const int d = j & 63;
            dst[(((size_t)(b * HH + h)) * SS + s) * HD + d] = acc[ii][jj] + bias[j];
        }
    }
}

// ---------------------------------------------------------------------------
// Fused attention per (b, h, 16-row q-block). 512 threads (16 warps).
//   Phase 1: scores[16][2048] = 1/(8 * Q Kt) in 256-col chunks, 4x2 microtile.
//            K chunk loaded COALESCED, stored transposed with XOR swizzle:
//            kv[d*256 + (row ^ ((d&60)>>1))] -> conflict-free STS and LDS.
//   Phase 2: softmax, one warp per row.
//   Phase 3: attn_mean += attn/H via red.global.add.v4.f32.
//   Phase 4: out = attn @ V; V chunk is a straight contiguous copy into smem
//            (row-major [256][64]); 8-way k-split; reduction reuses kv.
// SMEM: sc 16x2048 (128KB) | kv 17408 f | qt [64][16] => 200KB dynamic.
// ---------------------------------------------------------------------------
#define SMEM_FLOATS (32768 + 17408 + 1024)
#define SMEM_BYTES  (SMEM_FLOATS * 4)

__global__ void __launch_bounds__(512) attn_kernel(float* __restrict__ out)
{
    extern __shared__ float sm[];
    float* sc  = sm;                      // scores / attn, [16][2048]
    float* kv  = sm + 32768;              // K^T swizzled / V row-major / red
    float* qt  = sm + 32768 + 17408;      // Q^T [64][16]

    const int cta = blockIdx.x;           // b*2048 + h*128 + qb
    const int qb  = cta & 127;
    const int h   = (cta >> 7) & 15;
    const int b   = cta >> 11;
    const int q0  = qb * 16;
    const int tid = threadIdx.x;

    const float* Qg = g_Q + ((size_t)(b * HH + h) * SS + q0) * HD;
    const float* Kg = g_K + (size_t)(b * HH + h) * SS * HD;
    const float* Vg = g_V + (size_t)(b * HH + h) * SS * HD;

    // Load Q tile transposed: qt[d][r]  (first 256 threads; one-time, small)
    if (tid < 256) {
        const int r  = tid >> 4;
        const int c4 = (tid & 15) * 4;
        float4 v = *(const float4*)&Qg[r * HD + c4];
        qt[(c4 + 0) * 16 + r] = v.x;
        qt[(c4 + 1) * 16 + r] = v.y;
        qt[(c4 + 2) * 16 + r] = v.z;
        qt[(c4 + 3) * 16 + r] = v.w;
    }

    // ---- Phase 1: scores = 1 / (8 * Q K^T) ----
    const int rg  = tid >> 7;         // 0..3 -> q rows rg*4..rg*4+3
    const int cg  = tid & 127;        // 0..127 -> k cols cg*2..cg*2+1
    const int r0  = rg * 4;
    const int cg2 = cg * 2;

    for (int kc = 0; kc < 8; kc++) {
        // Coalesced load of K chunk (256 rows x 64 d), transpose into
        // XOR-swizzled kv[d][row].
        const float* Kc = Kg + (size_t)kc * 256 * HD;
#pragma unroll
        for (int i = 0; i < 8; i++) {
            const int f   = tid + i * 512;     // float4 index 0..4095
            const int row = f >> 4;
            const int d   = (f & 15) * 4;      // multiple of 4
            const int rw  = row ^ (d >> 1);    // (d&60)>>1 == d>>1 here
            float4 v = *(const float4*)(Kc + (size_t)f * 4);
            kv[(d + 0) * 256 + rw] = v.x;
            kv[(d + 1) * 256 + rw] = v.y;
            kv[(d + 2) * 256 + rw] = v.z;
            kv[(d + 3) * 256 + rw] = v.w;
        }
        __syncthreads();

        float acc[4][2];
#pragma unroll
        for (int i = 0; i < 4; i++) { acc[i][0] = 0.0f; acc[i][1] = 0.0f; }

#pragma unroll 8
        for (int d = 0; d < 64; d++) {
            float qv[4], kvv[2];
            *(float4*)qv  = *(const float4*)&qt[d * 16 + r0];   // broadcast
            const int m = (d & 60) >> 1;
            *(float2*)kvv = *(const float2*)&kv[d * 256 + (cg2 ^ m)];
#pragma unroll
            for (int i = 0; i < 4; i++) {
                acc[i][0] = fmaf(qv[i], kvv[0], acc[i][0]);
                acc[i][1] = fmaf(qv[i], kvv[1], acc[i][1]);
            }
        }

#pragma unroll
        for (int i = 0; i < 4; i++) {
            float2 sv;
            sv.x = __fdividef(1.0f, 8.0f * acc[i][0]);
            sv.y = __fdividef(1.0f, 8.0f * acc[i][1]);
            *(float2*)&sc[(r0 + i) * 2048 + kc * 256 + cg2] = sv;
        }
        __syncthreads();  // kv reuse guard
    }

    // ---- Phase 2: softmax per row (one warp per row) ----
    {
        const int warp = tid >> 5;    // 0..15 == row
        const int lane = tid & 31;
        float* row = sc + warp * 2048;
        float m = -3.4e38f;
        for (int k = lane; k < 2048; k += 32) m = fmaxf(m, row[k]);
#pragma unroll
        for (int o = 16; o; o >>= 1) m = fmaxf(m, __shfl_xor_sync(0xffffffffu, m, o));
        float ssum = 0.0f;
        for (int k = lane; k < 2048; k += 32) {
            float e = __expf(row[k] - m);
            row[k] = e;
            ssum += e;
        }
#pragma unroll
        for (int o = 16; o; o >>= 1) ssum += __shfl_xor_sync(0xffffffffu, ssum, o);
        const float inv = __fdividef(1.0f, ssum);
        for (int k = lane; k < 2048; k += 32) row[k] *= inv;
    }
    __syncthreads();

    // ---- Phase 3: attn_mean += attn / H  (vectorized global reduction) ----
    {
        float* am = out + (size_t)BB * SS * DD;
        for (int idx4 = tid; idx4 < 8192; idx4 += 512) {
            const int rr = idx4 >> 9;             // row 0..15
            const int kk = (idx4 & 511) * 4;      // col (x4)
            float4 v = *(const float4*)&sc[rr * 2048 + kk];
            v.x *= 0.0625f; v.y *= 0.0625f; v.z *= 0.0625f; v.w *= 0.0625f;
            float* p = &am[((size_t)(b * SS + q0 + rr)) * SS + kk];
            asm volatile("red.global.add.v4.f32 [%0], {%1, %2, %3, %4};"
                         :: "l"(p), "f"(v.x), "f"(v.y), "f"(v.z), "f"(v.w)
                         : "memory");
        }
    }

    // ---- Phase 4: out = attn @ V (V row-major copy, 4x4x4k tile) ----
    {
        const int dg  = tid & 15;          // d-cols dg*4
        const int rgq = (tid >> 4) & 3;    // rows rgq*4
        const int kg  = tid >> 6;          // 8 k-split groups
        const int rr0 = rgq * 4;

        float acc2[4][4];
#pragma unroll
        for (int i = 0; i < 4; i++)
#pragma unroll
            for (int j = 0; j < 4; j++) acc2[i][j] = 0.0f;

        for (int vc = 0; vc < 8; vc++) {
            // Coalesced contiguous copy: V chunk [256][64] row-major.
            const float4* Vc4 = (const float4*)(Vg + (size_t)vc * 256 * HD);
            float4* kv4 = (float4*)kv;
#pragma unroll
            for (int i = 0; i < 8; i++)
                kv4[tid + i * 512] = Vc4[tid + i * 512];
            __syncthreads();

            const float* scb = sc + vc * 256;
#pragma unroll 2
            for (int kk2 = 0; kk2 < 32; kk2 += 4) {
                const int k = kg * 32 + kk2;
                float a[4][4], vr[4][4];
#pragma unroll
                for (int i = 0; i < 4; i++)
                    *(float4*)a[i] = *(const float4*)&scb[(rr0 + i) * 2048 + k];
#pragma unroll
                for (int j = 0; j < 4; j++)
                    *(float4*)vr[j] = *(const float4*)&kv[(k + j) * 64 + dg * 4];
#pragma unroll
                for (int i = 0; i < 4; i++)
#pragma unroll
                    for (int j = 0; j < 4; j++)
#pragma unroll
                        for (int t = 0; t < 4; t++)
                            acc2[i][j] = fmaf(a[i][t], vr[t][j], acc2[i][j]);
            }
            __syncthreads();
        }

        // Cross-kg reduction: reuse kv buffer (8 groups x 16 rows x 64 cols).
        float* red = kv;
#pragma unroll
        for (int i = 0; i < 4; i++) {
            float4 v = make_float4(acc2[i][0], acc2[i][1], acc2[i][2], acc2[i][3]);
            *(float4*)&red[(kg * 16 + rr0 + i) * 64 + dg * 4] = v;
        }
        __syncthreads();

        for (int e = tid; e < 16 * 64; e += 512) {
            const int r = e >> 6;
            const int d = e & 63;
            float v = 0.0f;
#pragma unroll
            for (int g = 0; g < 8; g++) v += red[(g * 16 + r) * 64 + d];
            out[((size_t)(b * SS + q0 + r)) * DD + h * HD + d] = v;
        }
    }
}

// ---------------------------------------------------------------------------
extern "C" void kernel_launch(void* const* d_in, const int* in_sizes, int n_in,
                              void* d_out, int out_size)
{
    const float* query = (const float*)d_in[0];
    const float* key_  = (const float*)d_in[1];
    const float* value = (const float*)d_in[2];
    const float* Wq    = (const float*)d_in[3];
    const float* bq    = (const float*)d_in[4];
    const float* Wk    = (const float*)d_in[5];
    const float* bk    = (const float*)d_in[6];
    const float* Wv    = (const float*)d_in[7];
    const float* bv    = (const float*)d_in[8];
    float* out = (float*)d_out;

    // Zero the attn_mean accumulation region (after the [B,S,D] out block).
    cudaMemsetAsync(out + (size_t)BB * SS * DD, 0,
                    (size_t)BB * SS * SS * sizeof(float));

    dim3 pg(DD / 128, (BB * SS) / 128);
    proj_kernel<<<pg, 256>>>(query, Wq, bq, 0);
    proj_kernel<<<pg, 256>>>(key_,  Wk, bk, 1);
    proj_kernel<<<pg, 256>>>(value, Wv, bv, 2);

    cudaFuncSetAttribute(attn_kernel,
                         cudaFuncAttributeMaxDynamicSharedMemorySize, SMEM_BYTES);
    attn_kernel<<<BB * HH * (SS / 16), 512, SMEM_BYTES>>>(out);
}

// round 6
// speedup vs baseline: 1.6813x; 1.1459x over previous
#include <cuda_runtime.h>
#include <cstdint>

#define BB 2
#define SS 2048
#define DD 1024
#define HH 16
#define HD 64

// Scratch for head-split projections: [B,H,S,64] each, 16MB x3 static.
__device__ float g_Q[BB*HH*SS*HD];
__device__ float g_K[BB*HH*SS*HD];
__device__ float g_V[BB*HH*SS*HD];

// ---------------------------------------------------------------------------
// tf32 mma.sync helpers (sm_80+ PTX, works on plain sm_100 target)
// ---------------------------------------------------------------------------
__device__ __forceinline__ uint32_t f2tf32(float x) {
    uint32_t r;
    asm("cvt.rna.tf32.f32 %0, %1;" : "=r"(r) : "f"(x));
    return r;
}
__device__ __forceinline__ void split_tf32(float v, float& hi, float& lo) {
    uint32_t hb;
    asm("cvt.rna.tf32.f32 %0, %1;" : "=r"(hb) : "f"(v));
    hi = __uint_as_float(hb);
    float r = v - hi;
    uint32_t lb;
    asm("cvt.rna.tf32.f32 %0, %1;" : "=r"(lb) : "f"(r));
    lo = __uint_as_float(lb);
}
// D(16x8) += A(16x8,row) * B(8x8,col); tf32 in, f32 accum.
__device__ __forceinline__ void mma8(float* c, const uint32_t* a, const uint32_t* bf) {
    asm volatile("mma.sync.aligned.m16n8k8.row.col.f32.tf32.tf32.f32 "
                 "{%0,%1,%2,%3}, {%4,%5,%6,%7}, {%8,%9}, {%0,%1,%2,%3};"
                 : "+f"(c[0]), "+f"(c[1]), "+f"(c[2]), "+f"(c[3])
                 : "r"(a[0]), "r"(a[1]), "r"(a[2]), "r"(a[3]),
                   "r"(bf[0]), "r"(bf[1]));
}

// ---------------------------------------------------------------------------
// Q/K projections, fp32 SIMT (PRECISION-CRITICAL: feeds reciprocal scores).
// y[i][j] = sum_k X[i][k] * W[j][k] + bias[j]; grid (8, 32, 2).
// ---------------------------------------------------------------------------
__global__ void __launch_bounds__(256) proj_qk(const float* __restrict__ Xq,
                                               const float* __restrict__ Xk,
                                               const float* __restrict__ Wq,
                                               const float* __restrict__ Wk,
                                               const float* __restrict__ bq,
                                               const float* __restrict__ bk)
{
    const int z = blockIdx.z;
    const float* X    = z ? Xk : Xq;
    const float* W    = z ? Wk : Wq;
    const float* bias = z ? bk : bq;
    float* dst        = z ? g_K : g_Q;

    __shared__ float As[8][128];
    __shared__ float Bs[8][128];

    const int bi = blockIdx.y * 128;
    const int bj = blockIdx.x * 128;
    const int tid = threadIdx.x;
    const int tx = tid & 15;
    const int ty = tid >> 4;
    const int lr = tid >> 1;
    const int lc = (tid & 1) * 4;

    const float* Xp = X + (size_t)(bi + lr) * DD + lc;
    const float* Wp = W + (size_t)(bj + lr) * DD + lc;

    float acc[8][8];
#pragma unroll
    for (int i = 0; i < 8; i++)
#pragma unroll
        for (int j = 0; j < 8; j++) acc[i][j] = 0.0f;

    for (int k0 = 0; k0 < DD; k0 += 8) {
        float4 a4 = *(const float4*)(Xp + k0);
        float4 w4 = *(const float4*)(Wp + k0);
        As[lc + 0][lr] = a4.x; As[lc + 1][lr] = a4.y;
        As[lc + 2][lr] = a4.z; As[lc + 3][lr] = a4.w;
        Bs[lc + 0][lr] = w4.x; Bs[lc + 1][lr] = w4.y;
        Bs[lc + 2][lr] = w4.z; Bs[lc + 3][lr] = w4.w;
        __syncthreads();

#pragma unroll
        for (int k = 0; k < 8; k++) {
            float a[8], bb[8];
            *(float4*)&a[0]  = *(const float4*)&As[k][ty * 8];
            *(float4*)&a[4]  = *(const float4*)&As[k][ty * 8 + 4];
            *(float4*)&bb[0] = *(const float4*)&Bs[k][tx * 8];
            *(float4*)&bb[4] = *(const float4*)&Bs[k][tx * 8 + 4];
#pragma unroll
            for (int i = 0; i < 8; i++)
#pragma unroll
                for (int j = 0; j < 8; j++)
                    acc[i][j] = fmaf(a[i], bb[j], acc[i][j]);
        }
        __syncthreads();
    }

#pragma unroll
    for (int ii = 0; ii < 8; ii++) {
        const int i = bi + ty * 8 + ii;
        const int b = i >> 11;
        const int s = i & 2047;
#pragma unroll
        for (int jj = 0; jj < 8; jj++) {
            const int j = bj + tx * 8 + jj;
            const int h = j >> 6;
            const int d = j & 63;
            dst[(((size_t)(b * HH + h)) * SS + s) * HD + d] = acc[ii][jj] + bias[j];
        }
    }
}

// ---------------------------------------------------------------------------
// V projection via 3xTF32 mma.sync (V error does NOT amplify: terminal path).
// Grid (8, 32); 256 threads = 8 warps; CTA tile 128x128, K-chunks of 32.
// SMEM: Xhi/Xlo/Whi/Wlo each [128][36] (pad -> conflict-free frag LDS).
// ---------------------------------------------------------------------------
#define PJ_STR 36
#define PROJ_SMEM (4 * 128 * PJ_STR * 4)

__global__ void __launch_bounds__(256, 2)
proj_v_mma(const float* __restrict__ X, const float* __restrict__ W,
           const float* __restrict__ bias)
{
    extern __shared__ float ps[];
    float* sXh = ps;
    float* sXl = ps + 128 * PJ_STR;
    float* sWh = ps + 2 * 128 * PJ_STR;
    float* sWl = ps + 3 * 128 * PJ_STR;
    float* dst = g_V;

    const int bi = blockIdx.y * 128;
    const int bj = blockIdx.x * 128;
    const int tid  = threadIdx.x;
    const int wid  = tid >> 5;
    const int lane = tid & 31;
    const int wm = wid >> 2;
    const int wn = wid & 3;
    const int lr = lane >> 2;
    const int lc = lane & 3;

    float c[4][4][4];
#pragma unroll
    for (int i = 0; i < 4; i++)
#pragma unroll
        for (int j = 0; j < 4; j++)
#pragma unroll
            for (int e = 0; e < 4; e++) c[i][j][e] = 0.0f;

    for (int ch = 0; ch < 32; ch++) {
        const int k0 = ch * 32;
#pragma unroll
        for (int it = 0; it < 4; it++) {
            const int idx = tid + it * 256;
            const int row = idx >> 3;
            const int q   = (idx & 7) * 4;
            float4 xv = *(const float4*)&X[(size_t)(bi + row) * DD + k0 + q];
            float4 wv = *(const float4*)&W[(size_t)(bj + row) * DD + k0 + q];
            float xh[4], xl[4], wh[4], wl[4];
            const float* xs = (const float*)&xv;
            const float* ws = (const float*)&wv;
#pragma unroll
            for (int e = 0; e < 4; e++) {
                split_tf32(xs[e], xh[e], xl[e]);
                split_tf32(ws[e], wh[e], wl[e]);
            }
            *(float4*)&sXh[row * PJ_STR + q] = *(float4*)xh;
            *(float4*)&sXl[row * PJ_STR + q] = *(float4*)xl;
            *(float4*)&sWh[row * PJ_STR + q] = *(float4*)wh;
            *(float4*)&sWl[row * PJ_STR + q] = *(float4*)wl;
        }
        __syncthreads();

#pragma unroll
        for (int k8 = 0; k8 < 4; k8++) {
            const int kc = k8 * 8;
            uint32_t bh[4][2], bl[4][2];
#pragma unroll
            for (int nt = 0; nt < 4; nt++) {
                const int nr = (wn * 32 + nt * 8 + lr) * PJ_STR + kc + lc;
                bh[nt][0] = __float_as_uint(sWh[nr]);
                bh[nt][1] = __float_as_uint(sWh[nr + 4]);
                bl[nt][0] = __float_as_uint(sWl[nr]);
                bl[nt][1] = __float_as_uint(sWl[nr + 4]);
            }
#pragma unroll
            for (int mt = 0; mt < 4; mt++) {
                const int ar = (wm * 64 + mt * 16 + lr) * PJ_STR + kc + lc;
                uint32_t ah[4], al[4];
                ah[0] = __float_as_uint(sXh[ar]);
                ah[1] = __float_as_uint(sXh[ar + 8 * PJ_STR]);
                ah[2] = __float_as_uint(sXh[ar + 4]);
                ah[3] = __float_as_uint(sXh[ar + 8 * PJ_STR + 4]);
                al[0] = __float_as_uint(sXl[ar]);
                al[1] = __float_as_uint(sXl[ar + 8 * PJ_STR]);
                al[2] = __float_as_uint(sXl[ar + 4]);
                al[3] = __float_as_uint(sXl[ar + 8 * PJ_STR + 4]);
#pragma unroll
                for (int nt = 0; nt < 4; nt++) {
                    mma8(c[mt][nt], ah, bh[nt]);   // hi*hi
                    mma8(c[mt][nt], ah, bl[nt]);   // hi*lo
                    mma8(c[mt][nt], al, bh[nt]);   // lo*hi
                }
            }
        }
        __syncthreads();
    }

#pragma unroll
    for (int mt = 0; mt < 4; mt++) {
        const int i0 = bi + wm * 64 + mt * 16 + lr;
#pragma unroll
        for (int nt = 0; nt < 4; nt++) {
            const int j = bj + wn * 32 + nt * 8 + 2 * lc;
            const float b0 = bias[j], b1 = bias[j + 1];
            const int h = j >> 6;
            const int d = j & 63;
            {
                const int bb = i0 >> 11, s = i0 & 2047;
                float2 v = make_float2(c[mt][nt][0] + b0, c[mt][nt][1] + b1);
                *(float2*)&dst[(((size_t)(bb * HH + h)) * SS + s) * HD + d] = v;
            }
            {
                const int i1 = i0 + 8;
                const int bb = i1 >> 11, s = i1 & 2047;
                float2 v = make_float2(c[mt][nt][2] + b0, c[mt][nt][3] + b1);
                *(float2*)&dst[(((size_t)(bb * HH + h)) * SS + s) * HD + d] = v;
            }
        }
    }
}

// ---------------------------------------------------------------------------
// Fused attention per (b, h, 16-row q-block). 512 threads (16 warps).
//   Phase 1: fp32 FFMA QK^T (PRECISION-CRITICAL — do not touch).
//   Phase 2: softmax, one warp per row.
//   Phase 3: attn_mean += attn/H via red.global.add.v4.f32.
//   Phase 4: attn @ V via single-TF32 mma.sync; 16-way k-split by warp.
// sc row stride 2052 (bank = 4r + c -> frag LDS conflict-free).
// ---------------------------------------------------------------------------
#define SC_STR 2052
#define SMEM_FLOATS (16 * SC_STR + 17408 + 1024)
#define SMEM_BYTES  (SMEM_FLOATS * 4)

__global__ void __launch_bounds__(512) attn_kernel(float* __restrict__ out)
{
    extern __shared__ float sm[];
    float* sc  = sm;                      // scores / attn, [16][2052]
    float* kv  = sm + 16 * SC_STR;        // K^T swizzled / V [256][68] / red
    float* qt  = sm + 16 * SC_STR + 17408;// Q^T [64][16]

    const int cta = blockIdx.x;
    const int qb  = cta & 127;
    const int h   = (cta >> 7) & 15;
    const int b   = cta >> 11;
    const int q0  = qb * 16;
    const int tid = threadIdx.x;
    const int wid  = tid >> 5;
    const int lane = tid & 31;

    const float* Qg = g_Q + ((size_t)(b * HH + h) * SS + q0) * HD;
    const float* Kg = g_K + (size_t)(b * HH + h) * SS * HD;
    const float* Vg = g_V + (size_t)(b * HH + h) * SS * HD;

    if (tid < 256) {
        const int r  = tid >> 4;
        const int c4 = (tid & 15) * 4;
        float4 v = *(const float4*)&Qg[r * HD + c4];
        qt[(c4 + 0) * 16 + r] = v.x;
        qt[(c4 + 1) * 16 + r] = v.y;
        qt[(c4 + 2) * 16 + r] = v.z;
        qt[(c4 + 3) * 16 + r] = v.w;
    }

    // ---- Phase 1: scores = 1 / (8 * Q K^T), fp32 ----
    const int rg  = tid >> 7;
    const int cg  = tid & 127;
    const int r0  = rg * 4;
    const int cg2 = cg * 2;

    for (int kc = 0; kc < 8; kc++) {
        const float* Kc = Kg + (size_t)kc * 256 * HD;
#pragma unroll
        for (int i = 0; i < 8; i++) {
            const int f   = tid + i * 512;
            const int row = f >> 4;
            const int d   = (f & 15) * 4;
            const int rw  = row ^ (d >> 1);
            float4 v = *(const float4*)(Kc + (size_t)f * 4);
            kv[(d + 0) * 256 + rw] = v.x;
            kv[(d + 1) * 256 + rw] = v.y;
            kv[(d + 2) * 256 + rw] = v.z;
            kv[(d + 3) * 256 + rw] = v.w;
        }
        __syncthreads();

        float acc[4][2];
#pragma unroll
        for (int i = 0; i < 4; i++) { acc[i][0] = 0.0f; acc[i][1] = 0.0f; }

#pragma unroll 8
        for (int d = 0; d < 64; d++) {
            float qv[4], kvv[2];
            *(float4*)qv  = *(const float4*)&qt[d * 16 + r0];
            const int m = (d & 60) >> 1;
            *(float2*)kvv = *(const float2*)&kv[d * 256 + (cg2 ^ m)];
#pragma unroll
            for (int i = 0; i < 4; i++) {
                acc[i][0] = fmaf(qv[i], kvv[0], acc[i][0]);
                acc[i][1] = fmaf(qv[i], kvv[1], acc[i][1]);
            }
        }

#pragma unroll
        for (int i = 0; i < 4; i++) {
            float2 sv;
            sv.x = __fdividef(1.0f, 8.0f * acc[i][0]);
            sv.y = __fdividef(1.0f, 8.0f * acc[i][1]);
            *(float2*)&sc[(r0 + i) * SC_STR + kc * 256 + cg2] = sv;
        }
        __syncthreads();
    }

    // ---- Phase 2: softmax per row (one warp per row) ----
    {
        float* row = sc + wid * SC_STR;
        float m = -3.4e38f;
        for (int k = lane; k < 2048; k += 32) m = fmaxf(m, row[k]);
#pragma unroll
        for (int o = 16; o; o >>= 1) m = fmaxf(m, __shfl_xor_sync(0xffffffffu, m, o));
        float ssum = 0.0f;
        for (int k = lane; k < 2048; k += 32) {
            float e = __expf(row[k] - m);
            row[k] = e;
            ssum += e;
        }
#pragma unroll
        for (int o = 16; o; o >>= 1) ssum += __shfl_xor_sync(0xffffffffu, ssum, o);
        const float inv = __fdividef(1.0f, ssum);
        for (int k = lane; k < 2048; k += 32) row[k] *= inv;
    }
    __syncthreads();

    // ---- Phase 3: attn_mean += attn / H ----
    {
        float* am = out + (size_t)BB * SS * DD;
        for (int idx4 = tid; idx4 < 8192; idx4 += 512) {
            const int rr = idx4 >> 9;
            const int kk = (idx4 & 511) * 4;
            float4 v = *(const float4*)&sc[rr * SC_STR + kk];
            v.x *= 0.0625f; v.y *= 0.0625f; v.z *= 0.0625f; v.w *= 0.0625f;
            float* p = &am[((size_t)(b * SS + q0 + rr)) * SS + kk];
            asm volatile("red.global.add.v4.f32 [%0], {%1, %2, %3, %4};"
                         :: "l"(p), "f"(v.x), "f"(v.y), "f"(v.z), "f"(v.w)
                         : "memory");
        }
    }

    // ---- Phase 4: out = attn @ V via tf32 mma (16-way k-split by warp) ----
    {
        const int lr = lane >> 2;
        const int lc = lane & 3;

        float c[8][4];
#pragma unroll
        for (int nt = 0; nt < 8; nt++)
#pragma unroll
            for (int e = 0; e < 4; e++) c[nt][e] = 0.0f;

        for (int vc = 0; vc < 8; vc++) {
            const float4* Vc4 = (const float4*)(Vg + (size_t)vc * 256 * HD);
#pragma unroll
            for (int i = 0; i < 8; i++) {
                const int f   = tid + i * 512;
                const int row = f >> 4;
                const int nq  = (f & 15) * 4;
                *(float4*)&kv[row * 68 + nq] = Vc4[f];
            }
            __syncthreads();

#pragma unroll
            for (int t = 0; t < 2; t++) {
                const int kc = (wid * 2 + t) * 8;
                uint32_t a[4];
                const int ac = vc * 256 + kc + lc;
                a[0] = f2tf32(sc[lr * SC_STR + ac]);
                a[1] = f2tf32(sc[(lr + 8) * SC_STR + ac]);
                a[2] = f2tf32(sc[lr * SC_STR + ac + 4]);
                a[3] = f2tf32(sc[(lr + 8) * SC_STR + ac + 4]);
#pragma unroll
                for (int nt = 0; nt < 8; nt++) {
                    uint32_t bf[2];
                    const int n = nt * 8 + lr;
                    bf[0] = f2tf32(kv[(kc + lc) * 68 + n]);
                    bf[1] = f2tf32(kv[(kc + lc + 4) * 68 + n]);
                    mma8(c[nt], a, bf);
                }
            }
            __syncthreads();
        }

        // Cross-warp reduction: red[16 warps][16][64] reuses kv.
        float* red = kv;
#pragma unroll
        for (int nt = 0; nt < 8; nt++) {
            const int col = nt * 8 + 2 * lc;
            red[wid * 1024 + lr * 64 + col]           = c[nt][0];
            red[wid * 1024 + lr * 64 + col + 1]       = c[nt][1];
            red[wid * 1024 + (lr + 8) * 64 + col]     = c[nt][2];
            red[wid * 1024 + (lr + 8) * 64 + col + 1] = c[nt][3];
        }
        __syncthreads();

        for (int e = tid; e < 1024; e += 512) {
            const int r = e >> 6;
            const int d = e & 63;
            float v = 0.0f;
#pragma unroll
            for (int g = 0; g < 16; g++) v += red[g * 1024 + e];
            out[((size_t)(b * SS + q0 + r)) * DD + h * HD + d] = v;
        }
    }
}

// ---------------------------------------------------------------------------
extern "C" void kernel_launch(void* const* d_in, const int* in_sizes, int n_in,
                              void* d_out, int out_size)
{
    const float* query = (const float*)d_in[0];
    const float* key_  = (const float*)d_in[1];
    const float* value = (const float*)d_in[2];
    const float* Wq    = (const float*)d_in[3];
    const float* bq    = (const float*)d_in[4];
    const float* Wk    = (const float*)d_in[5];
    const float* bk    = (const float*)d_in[6];
    const float* Wv    = (const float*)d_in[7];
    const float* bv    = (const float*)d_in[8];
    float* out = (float*)d_out;

    cudaMemsetAsync(out + (size_t)BB * SS * DD, 0,
                    (size_t)BB * SS * SS * sizeof(float));

    // Q,K: fp32 SIMT (precision-critical). V: 3xTF32 tensor cores.
    dim3 pg(DD / 128, (BB * SS) / 128, 2);
    proj_qk<<<pg, 256>>>(query, key_, Wq, Wk, bq, bk);

    cudaFuncSetAttribute(proj_v_mma,
                         cudaFuncAttributeMaxDynamicSharedMemorySize, PROJ_SMEM);
    dim3 pv(DD / 128, (BB * SS) / 128);
    proj_v_mma<<<pv, 256, PROJ_SMEM>>>(value, Wv, bv);

    cudaFuncSetAttribute(attn_kernel,
                         cudaFuncAttributeMaxDynamicSharedMemorySize, SMEM_BYTES);
    attn_kernel<<<BB * HH * (SS / 16), 512, SMEM_BYTES>>>(out);
}

// round 7
// speedup vs baseline: 1.7074x; 1.0155x over previous
#include <cuda_runtime.h>
#include <cstdint>

#define BB 2
#define SS 2048
#define DD 1024
#define HH 16
#define HD 64

// Scratch for head-split projections: [B,H,S,64] each, 16MB x3 static.
__device__ float g_Q[BB*HH*SS*HD];
__device__ float g_K[BB*HH*SS*HD];
__device__ float g_V[BB*HH*SS*HD];

// ---------------------------------------------------------------------------
// Packed f32x2 helpers (sm_100 base feature, PTX ISA 8.6). Each lane is an
// exact IEEE fp32 FMA -> NO precision change vs scalar FFMA.
// ---------------------------------------------------------------------------
typedef unsigned long long u64cu;
union F4U2 { float4 f4; u64cu u2[2]; };

__device__ __forceinline__ u64cu dup2(float x) {
    u64cu r; asm("mov.b64 %0, {%1, %1};" : "=l"(r) : "f"(x)); return r;
}
__device__ __forceinline__ void fma2(u64cu& c, u64cu a, u64cu b) {
    asm("fma.rn.f32x2 %0, %1, %2, %0;" : "+l"(c) : "l"(a), "l"(b));
}
__device__ __forceinline__ float2 up2(u64cu v) {
    float2 f; asm("mov.b64 {%0, %1}, %2;" : "=f"(f.x), "=f"(f.y) : "l"(v));
    return f;
}

// ---------------------------------------------------------------------------
// tf32 mma.sync helpers (sm_80+ PTX, works on plain sm_100 target)
// ---------------------------------------------------------------------------
__device__ __forceinline__ uint32_t f2tf32(float x) {
    uint32_t r;
    asm("cvt.rna.tf32.f32 %0, %1;" : "=r"(r) : "f"(x));
    return r;
}
__device__ __forceinline__ void split_tf32(float v, float& hi, float& lo) {
    uint32_t hb;
    asm("cvt.rna.tf32.f32 %0, %1;" : "=r"(hb) : "f"(v));
    hi = __uint_as_float(hb);
    float r = v - hi;
    uint32_t lb;
    asm("cvt.rna.tf32.f32 %0, %1;" : "=r"(lb) : "f"(r));
    lo = __uint_as_float(lb);
}
__device__ __forceinline__ void mma8(float* c, const uint32_t* a, const uint32_t* bf) {
    asm volatile("mma.sync.aligned.m16n8k8.row.col.f32.tf32.tf32.f32 "
                 "{%0,%1,%2,%3}, {%4,%5,%6,%7}, {%8,%9}, {%0,%1,%2,%3};"
                 : "+f"(c[0]), "+f"(c[1]), "+f"(c[2]), "+f"(c[3])
                 : "r"(a[0]), "r"(a[1]), "r"(a[2]), "r"(a[3]),
                   "r"(bf[0]), "r"(bf[1]));
}

// ---------------------------------------------------------------------------
// Q/K projections, fp32 via f32x2 (PRECISION-CRITICAL path, exact fp32 math).
// y[i][j] = sum_k X[i][k] * W[j][k] + bias[j]; grid (8, 32, 2).
// ---------------------------------------------------------------------------
__global__ void __launch_bounds__(256) proj_qk(const float* __restrict__ Xq,
                                               const float* __restrict__ Xk,
                                               const float* __restrict__ Wq,
                                               const float* __restrict__ Wk,
                                               const float* __restrict__ bq,
                                               const float* __restrict__ bk)
{
    const int z = blockIdx.z;
    const float* X    = z ? Xk : Xq;
    const float* W    = z ? Wk : Wq;
    const float* bias = z ? bk : bq;
    float* dst        = z ? g_K : g_Q;

    __shared__ float As[8][128];
    __shared__ float Bs[8][128];

    const int bi = blockIdx.y * 128;
    const int bj = blockIdx.x * 128;
    const int tid = threadIdx.x;
    const int tx = tid & 15;
    const int ty = tid >> 4;
    const int lr = tid >> 1;
    const int lc = (tid & 1) * 4;

    const float* Xp = X + (size_t)(bi + lr) * DD + lc;
    const float* Wp = W + (size_t)(bj + lr) * DD + lc;

    u64cu accp[8][4];
#pragma unroll
    for (int i = 0; i < 8; i++)
#pragma unroll
        for (int p = 0; p < 4; p++) accp[i][p] = 0ULL;

    for (int k0 = 0; k0 < DD; k0 += 8) {
        float4 a4 = *(const float4*)(Xp + k0);
        float4 w4 = *(const float4*)(Wp + k0);
        As[lc + 0][lr] = a4.x; As[lc + 1][lr] = a4.y;
        As[lc + 2][lr] = a4.z; As[lc + 3][lr] = a4.w;
        Bs[lc + 0][lr] = w4.x; Bs[lc + 1][lr] = w4.y;
        Bs[lc + 2][lr] = w4.z; Bs[lc + 3][lr] = w4.w;
        __syncthreads();

#pragma unroll
        for (int k = 0; k < 8; k++) {
            float av[8];
            F4U2 B0, B1;
            *(float4*)&av[0] = *(const float4*)&As[k][ty * 8];
            *(float4*)&av[4] = *(const float4*)&As[k][ty * 8 + 4];
            B0.f4 = *(const float4*)&Bs[k][tx * 8];
            B1.f4 = *(const float4*)&Bs[k][tx * 8 + 4];
            const u64cu bp0 = B0.u2[0], bp1 = B0.u2[1];
            const u64cu bp2 = B1.u2[0], bp3 = B1.u2[1];
#pragma unroll
            for (int i = 0; i < 8; i++) {
                const u64cu ai = dup2(av[i]);
                fma2(accp[i][0], ai, bp0);
                fma2(accp[i][1], ai, bp1);
                fma2(accp[i][2], ai, bp2);
                fma2(accp[i][3], ai, bp3);
            }
        }
        __syncthreads();
    }

    // Epilogue: unpack pairs, add bias, scatter into head-split layout.
#pragma unroll
    for (int ii = 0; ii < 8; ii++) {
        const int i = bi + ty * 8 + ii;
        const int b = i >> 11;
        const int s = i & 2047;
#pragma unroll
        for (int p = 0; p < 4; p++) {
            const int j = bj + tx * 8 + 2 * p;
            const int h = j >> 6;
            const int d = j & 63;
            float2 v = up2(accp[ii][p]);
            v.x += bias[j];
            v.y += bias[j + 1];
            *(float2*)&dst[(((size_t)(b * HH + h)) * SS + s) * HD + d] = v;
        }
    }
}

// ---------------------------------------------------------------------------
// V projection via 3xTF32 mma.sync (V error does NOT amplify: terminal path).
// ---------------------------------------------------------------------------
#define PJ_STR 36
#define PROJ_SMEM (4 * 128 * PJ_STR * 4)

__global__ void __launch_bounds__(256, 2)
proj_v_mma(const float* __restrict__ X, const float* __restrict__ W,
           const float* __restrict__ bias)
{
    extern __shared__ float ps[];
    float* sXh = ps;
    float* sXl = ps + 128 * PJ_STR;
    float* sWh = ps + 2 * 128 * PJ_STR;
    float* sWl = ps + 3 * 128 * PJ_STR;
    float* dst = g_V;

    const int bi = blockIdx.y * 128;
    const int bj = blockIdx.x * 128;
    const int tid  = threadIdx.x;
    const int wid  = tid >> 5;
    const int lane = tid & 31;
    const int wm = wid >> 2;
    const int wn = wid & 3;
    const int lr = lane >> 2;
    const int lc = lane & 3;

    float c[4][4][4];
#pragma unroll
    for (int i = 0; i < 4; i++)
#pragma unroll
        for (int j = 0; j < 4; j++)
#pragma unroll
            for (int e = 0; e < 4; e++) c[i][j][e] = 0.0f;

    for (int ch = 0; ch < 32; ch++) {
        const int k0 = ch * 32;
#pragma unroll
        for (int it = 0; it < 4; it++) {
            const int idx = tid + it * 256;
            const int row = idx >> 3;
            const int q   = (idx & 7) * 4;
            float4 xv = *(const float4*)&X[(size_t)(bi + row) * DD + k0 + q];
            float4 wv = *(const float4*)&W[(size_t)(bj + row) * DD + k0 + q];
            float xh[4], xl[4], wh[4], wl[4];
            const float* xs = (const float*)&xv;
            const float* ws = (const float*)&wv;
#pragma unroll
            for (int e = 0; e < 4; e++) {
                split_tf32(xs[e], xh[e], xl[e]);
                split_tf32(ws[e], wh[e], wl[e]);
            }
            *(float4*)&sXh[row * PJ_STR + q] = *(float4*)xh;
            *(float4*)&sXl[row * PJ_STR + q] = *(float4*)xl;
            *(float4*)&sWh[row * PJ_STR + q] = *(float4*)wh;
            *(float4*)&sWl[row * PJ_STR + q] = *(float4*)wl;
        }
        __syncthreads();

#pragma unroll
        for (int k8 = 0; k8 < 4; k8++) {
            const int kc = k8 * 8;
            uint32_t bh[4][2], bl[4][2];
#pragma unroll
            for (int nt = 0; nt < 4; nt++) {
                const int nr = (wn * 32 + nt * 8 + lr) * PJ_STR + kc + lc;
                bh[nt][0] = __float_as_uint(sWh[nr]);
                bh[nt][1] = __float_as_uint(sWh[nr + 4]);
                bl[nt][0] = __float_as_uint(sWl[nr]);
                bl[nt][1] = __float_as_uint(sWl[nr + 4]);
            }
#pragma unroll
            for (int mt = 0; mt < 4; mt++) {
                const int ar = (wm * 64 + mt * 16 + lr) * PJ_STR + kc + lc;
                uint32_t ah[4], al[4];
                ah[0] = __float_as_uint(sXh[ar]);
                ah[1] = __float_as_uint(sXh[ar + 8 * PJ_STR]);
                ah[2] = __float_as_uint(sXh[ar + 4]);
                ah[3] = __float_as_uint(sXh[ar + 8 * PJ_STR + 4]);
                al[0] = __float_as_uint(sXl[ar]);
                al[1] = __float_as_uint(sXl[ar + 8 * PJ_STR]);
                al[2] = __float_as_uint(sXl[ar + 4]);
                al[3] = __float_as_uint(sXl[ar + 8 * PJ_STR + 4]);
#pragma unroll
                for (int nt = 0; nt < 4; nt++) {
                    mma8(c[mt][nt], ah, bh[nt]);   // hi*hi
                    mma8(c[mt][nt], ah, bl[nt]);   // hi*lo
                    mma8(c[mt][nt], al, bh[nt]);   // lo*hi
                }
            }
        }
        __syncthreads();
    }

#pragma unroll
    for (int mt = 0; mt < 4; mt++) {
        const int i0 = bi + wm * 64 + mt * 16 + lr;
#pragma unroll
        for (int nt = 0; nt < 4; nt++) {
            const int j = bj + wn * 32 + nt * 8 + 2 * lc;
            const float b0 = bias[j], b1 = bias[j + 1];
            const int h = j >> 6;
            const int d = j & 63;
            {
                const int bb = i0 >> 11, s = i0 & 2047;
                float2 v = make_float2(c[mt][nt][0] + b0, c[mt][nt][1] + b1);
                *(float2*)&dst[(((size_t)(bb * HH + h)) * SS + s) * HD + d] = v;
            }
            {
                const int i1 = i0 + 8;
                const int bb = i1 >> 11, s = i1 & 2047;
                float2 v = make_float2(c[mt][nt][2] + b0, c[mt][nt][3] + b1);
                *(float2*)&dst[(((size_t)(bb * HH + h)) * SS + s) * HD + d] = v;
            }
        }
    }
}

// ---------------------------------------------------------------------------
// Fused attention per (b, h, 16-row q-block). 512 threads (16 warps).
//   Phase 1: fp32 QK^T via f32x2 (exact fp32 — precision-critical).
//   Phase 2: softmax, one warp per row.
//   Phase 3: attn_mean += attn/H via red.global.add.v4.f32.
//   Phase 4: attn @ V via single-TF32 mma.sync; 16-way k-split by warp.
// ---------------------------------------------------------------------------
#define SC_STR 2052
#define SMEM_FLOATS (16 * SC_STR + 17408 + 1024)
#define SMEM_BYTES  (SMEM_FLOATS * 4)

__global__ void __launch_bounds__(512) attn_kernel(float* __restrict__ out)
{
    extern __shared__ float sm[];
    float* sc  = sm;                      // scores / attn, [16][2052]
    float* kv  = sm + 16 * SC_STR;        // K^T swizzled / V [256][68] / red
    float* qt  = sm + 16 * SC_STR + 17408;// Q^T [64][16]

    const int cta = blockIdx.x;
    const int qb  = cta & 127;
    const int h   = (cta >> 7) & 15;
    const int b   = cta >> 11;
    const int q0  = qb * 16;
    const int tid = threadIdx.x;
    const int wid  = tid >> 5;
    const int lane = tid & 31;

    const float* Qg = g_Q + ((size_t)(b * HH + h) * SS + q0) * HD;
    const float* Kg = g_K + (size_t)(b * HH + h) * SS * HD;
    const float* Vg = g_V + (size_t)(b * HH + h) * SS * HD;

    if (tid < 256) {
        const int r  = tid >> 4;
        const int c4 = (tid & 15) * 4;
        float4 v = *(const float4*)&Qg[r * HD + c4];
        qt[(c4 + 0) * 16 + r] = v.x;
        qt[(c4 + 1) * 16 + r] = v.y;
        qt[(c4 + 2) * 16 + r] = v.z;
        qt[(c4 + 3) * 16 + r] = v.w;
    }

    // ---- Phase 1: scores = 1 / (8 * Q K^T), exact fp32 via f32x2 ----
    const int rg  = tid >> 7;
    const int cg  = tid & 127;
    const int r0  = rg * 4;
    const int cg2 = cg * 2;

    for (int kc = 0; kc < 8; kc++) {
        const float* Kc = Kg + (size_t)kc * 256 * HD;
#pragma unroll
        for (int i = 0; i < 8; i++) {
            const int f   = tid + i * 512;
            const int row = f >> 4;
            const int d   = (f & 15) * 4;
            const int rw  = row ^ (d >> 1);
            float4 v = *(const float4*)(Kc + (size_t)f * 4);
            kv[(d + 0) * 256 + rw] = v.x;
            kv[(d + 1) * 256 + rw] = v.y;
            kv[(d + 2) * 256 + rw] = v.z;
            kv[(d + 3) * 256 + rw] = v.w;
        }
        __syncthreads();

        // acc pairs over q-rows: (r0,r0+1),(r0+2,r0+3) x 2 k-cols.
        u64cu a01c0 = 0ULL, a23c0 = 0ULL, a01c1 = 0ULL, a23c1 = 0ULL;

#pragma unroll 8
        for (int d = 0; d < 64; d++) {
            F4U2 qv;
            qv.f4 = *(const float4*)&qt[d * 16 + r0];      // broadcast
            const u64cu q01 = qv.u2[0], q23 = qv.u2[1];
            const int m = (d & 60) >> 1;
            float2 kvv = *(const float2*)&kv[d * 256 + (cg2 ^ m)];
            const u64cu k0d = dup2(kvv.x);
            const u64cu k1d = dup2(kvv.y);
            fma2(a01c0, q01, k0d);
            fma2(a23c0, q23, k0d);
            fma2(a01c1, q01, k1d);
            fma2(a23c1, q23, k1d);
        }

        {
            float2 c0lo = up2(a01c0), c0hi = up2(a23c0);
            float2 c1lo = up2(a01c1), c1hi = up2(a23c1);
            float rowv[4][2] = {{c0lo.x, c1lo.x}, {c0lo.y, c1lo.y},
                                {c0hi.x, c1hi.x}, {c0hi.y, c1hi.y}};
#pragma unroll
            for (int i = 0; i < 4; i++) {
                float2 sv;
                sv.x = __fdividef(1.0f, 8.0f * rowv[i][0]);
                sv.y = __fdividef(1.0f, 8.0f * rowv[i][1]);
                *(float2*)&sc[(r0 + i) * SC_STR + kc * 256 + cg2] = sv;
            }
        }
        __syncthreads();
    }

    // ---- Phase 2: softmax per row (one warp per row) ----
    {
        float* row = sc + wid * SC_STR;
        float m = -3.4e38f;
        for (int k = lane; k < 2048; k += 32) m = fmaxf(m, row[k]);
#pragma unroll
        for (int o = 16; o; o >>= 1) m = fmaxf(m, __shfl_xor_sync(0xffffffffu, m, o));
        float ssum = 0.0f;
        for (int k = lane; k < 2048; k += 32) {
            float e = __expf(row[k] - m);
            row[k] = e;
            ssum += e;
        }
#pragma unroll
        for (int o = 16; o; o >>= 1) ssum += __shfl_xor_sync(0xffffffffu, ssum, o);
        const float inv = __fdividef(1.0f, ssum);
        for (int k = lane; k < 2048; k += 32) row[k] *= inv;
    }
    __syncthreads();

    // ---- Phase 3: attn_mean += attn / H ----
    {
        float* am = out + (size_t)BB * SS * DD;
        for (int idx4 = tid; idx4 < 8192; idx4 += 512) {
            const int rr = idx4 >> 9;
            const int kk = (idx4 & 511) * 4;
            float4 v = *(const float4*)&sc[rr * SC_STR + kk];
            v.x *= 0.0625f; v.y *= 0.0625f; v.z *= 0.0625f; v.w *= 0.0625f;
            float* p = &am[((size_t)(b * SS + q0 + rr)) * SS + kk];
            asm volatile("red.global.add.v4.f32 [%0], {%1, %2, %3, %4};"
                         :: "l"(p), "f"(v.x), "f"(v.y), "f"(v.z), "f"(v.w)
                         : "memory");
        }
    }

    // ---- Phase 4: out = attn @ V via tf32 mma (16-way k-split by warp) ----
    {
        const int lr = lane >> 2;
        const int lc = lane & 3;

        float c[8][4];
#pragma unroll
        for (int nt = 0; nt < 8; nt++)
#pragma unroll
            for (int e = 0; e < 4; e++) c[nt][e] = 0.0f;

        for (int vc = 0; vc < 8; vc++) {
            const float4* Vc4 = (const float4*)(Vg + (size_t)vc * 256 * HD);
#pragma unroll
            for (int i = 0; i < 8; i++) {
                const int f   = tid + i * 512;
                const int row = f >> 4;
                const int nq  = (f & 15) * 4;
                *(float4*)&kv[row * 68 + nq] = Vc4[f];
            }
            __syncthreads();

#pragma unroll
            for (int t = 0; t < 2; t++) {
                const int kc = (wid * 2 + t) * 8;
                uint32_t a[4];
                const int ac = vc * 256 + kc + lc;
                a[0] = f2tf32(sc[lr * SC_STR + ac]);
                a[1] = f2tf32(sc[(lr + 8) * SC_STR + ac]);
                a[2] = f2tf32(sc[lr * SC_STR + ac + 4]);
                a[3] = f2tf32(sc[(lr + 8) * SC_STR + ac + 4]);
#pragma unroll
                for (int nt = 0; nt < 8; nt++) {
                    uint32_t bf[2];
                    const int n = nt * 8 + lr;
                    bf[0] = f2tf32(kv[(kc + lc) * 68 + n]);
                    bf[1] = f2tf32(kv[(kc + lc + 4) * 68 + n]);
                    mma8(c[nt], a, bf);
                }
            }
            __syncthreads();
        }

        float* red = kv;
#pragma unroll
        for (int nt = 0; nt < 8; nt++) {
            const int col = nt * 8 + 2 * lc;
            red[wid * 1024 + lr * 64 + col]           = c[nt][0];
            red[wid * 1024 + lr * 64 + col + 1]       = c[nt][1];
            red[wid * 1024 + (lr + 8) * 64 + col]     = c[nt][2];
            red[wid * 1024 + (lr + 8) * 64 + col + 1] = c[nt][3];
        }
        __syncthreads();

        for (int e = tid; e < 1024; e += 512) {
            const int r = e >> 6;
            const int d = e & 63;
            float v = 0.0f;
#pragma unroll
            for (int g = 0; g < 16; g++) v += red[g * 1024 + e];
            out[((size_t)(b * SS + q0 + r)) * DD + h * HD + d] = v;
        }
    }
}

// ---------------------------------------------------------------------------
extern "C" void kernel_launch(void* const* d_in, const int* in_sizes, int n_in,
                              void* d_out, int out_size)
{
    const float* query = (const float*)d_in[0];
    const float* key_  = (const float*)d_in[1];
    const float* value = (const float*)d_in[2];
    const float* Wq    = (const float*)d_in[3];
    const float* bq    = (const float*)d_in[4];
    const float* Wk    = (const float*)d_in[5];
    const float* bk    = (const float*)d_in[6];
    const float* Wv    = (const float*)d_in[7];
    const float* bv    = (const float*)d_in[8];
    float* out = (float*)d_out;

    cudaMemsetAsync(out + (size_t)BB * SS * DD, 0,
                    (size_t)BB * SS * SS * sizeof(float));

    // Q,K: fp32 f32x2 (precision-critical). V: 3xTF32 tensor cores.
    dim3 pg(DD / 128, (BB * SS) / 128, 2);
    proj_qk<<<pg, 256>>>(query, key_, Wq, Wk, bq, bk);

    cudaFuncSetAttribute(proj_v_mma,
                         cudaFuncAttributeMaxDynamicSharedMemorySize, PROJ_SMEM);
    dim3 pv(DD / 128, (BB * SS) / 128);
    proj_v_mma<<<pv, 256, PROJ_SMEM>>>(value, Wv, bv);

    cudaFuncSetAttribute(attn_kernel,
                         cudaFuncAttributeMaxDynamicSharedMemorySize, SMEM_BYTES);
    attn_kernel<<<BB * HH * (SS / 16), 512, SMEM_BYTES>>>(out);
}

// round 10
// speedup vs baseline: 1.7098x; 1.0014x over previous
#include <cuda_runtime.h>
#include <cstdint>

#define BB 2
#define SS 2048
#define DD 1024
#define HH 16
#define HD 64

// Scratch: g_Q [b,h][s][64]; g_K TRANSPOSED [b,h][d][s]; g_V [b,h][s][64].
__device__ float g_Q[BB*HH*SS*HD];
__device__ float g_K[BB*HH*SS*HD];
__device__ float g_V[BB*HH*SS*HD];

// ---------------------------------------------------------------------------
// Packed f32x2 helpers (exact IEEE fp32 per lane).
// ---------------------------------------------------------------------------
typedef unsigned long long u64cu;
union F4U2 { float4 f4; u64cu u2[2]; };

__device__ __forceinline__ u64cu dup2(float x) {
    u64cu r; asm("mov.b64 %0, {%1, %1};" : "=l"(r) : "f"(x)); return r;
}
__device__ __forceinline__ void fma2(u64cu& c, u64cu a, u64cu b) {
    asm("fma.rn.f32x2 %0, %1, %2, %0;" : "+l"(c) : "l"(a), "l"(b));
}
__device__ __forceinline__ float2 up2(u64cu v) {
    float2 f; asm("mov.b64 {%0, %1}, %2;" : "=f"(f.x), "=f"(f.y) : "l"(v));
    return f;
}

// ---------------------------------------------------------------------------
// tf32 mma.sync helpers (downstream-of-softmax paths only).
// ---------------------------------------------------------------------------
__device__ __forceinline__ uint32_t f2tf32(float x) {
    uint32_t r;
    asm("cvt.rna.tf32.f32 %0, %1;" : "=r"(r) : "f"(x));
    return r;
}
__device__ __forceinline__ void split_tf32(float v, float& hi, float& lo) {
    uint32_t hb;
    asm("cvt.rna.tf32.f32 %0, %1;" : "=r"(hb) : "f"(v));
    hi = __uint_as_float(hb);
    float r = v - hi;
    uint32_t lb;
    asm("cvt.rna.tf32.f32 %0, %1;" : "=r"(lb) : "f"(r));
    lo = __uint_as_float(lb);
}
__device__ __forceinline__ void mma8(float* c, const uint32_t* a, const uint32_t* bf) {
    asm volatile("mma.sync.aligned.m16n8k8.row.col.f32.tf32.tf32.f32 "
                 "{%0,%1,%2,%3}, {%4,%5,%6,%7}, {%8,%9}, {%0,%1,%2,%3};"
                 : "+f"(c[0]), "+f"(c[1]), "+f"(c[2]), "+f"(c[3])
                 : "r"(a[0]), "r"(a[1]), "r"(a[2]), "r"(a[3]),
                   "r"(bf[0]), "r"(bf[1]));
}

// ---------------------------------------------------------------------------
// Q/K projections, fp32 (PRECISION-CRITICAL: tensor cores forbidden here).
// z=0 -> g_Q head-split [b,h][s][d]; z=1 -> g_K TRANSPOSED [b,h][d][s].
// ---------------------------------------------------------------------------
__global__ void __launch_bounds__(256) proj_qk(const float* __restrict__ Xq,
                                               const float* __restrict__ Xk,
                                               const float* __restrict__ Wq,
                                               const float* __restrict__ Wk,
                                               const float* __restrict__ bq,
                                               const float* __restrict__ bk)
{
    const int z = blockIdx.z;
    const float* X    = z ? Xk : Xq;
    const float* W    = z ? Wk : Wq;
    const float* bias = z ? bk : bq;
    float* dst        = z ? g_K : g_Q;

    __shared__ float As[8][128];
    __shared__ float Bs[8][128];

    const int bi = blockIdx.y * 128;
    const int bj = blockIdx.x * 128;
    const int tid = threadIdx.x;
    const int tx = tid & 15;
    const int ty = tid >> 4;
    const int lr = tid >> 1;
    const int lc = (tid & 1) * 4;

    const float* Xp = X + (size_t)(bi + lr) * DD + lc;
    const float* Wp = W + (size_t)(bj + lr) * DD + lc;

    u64cu accp[8][4];
#pragma unroll
    for (int i = 0; i < 8; i++)
#pragma unroll
        for (int p = 0; p < 4; p++) accp[i][p] = 0ULL;

    for (int k0 = 0; k0 < DD; k0 += 8) {
        float4 a4 = *(const float4*)(Xp + k0);
        float4 w4 = *(const float4*)(Wp + k0);
        As[lc + 0][lr] = a4.x; As[lc + 1][lr] = a4.y;
        As[lc + 2][lr] = a4.z; As[lc + 3][lr] = a4.w;
        Bs[lc + 0][lr] = w4.x; Bs[lc + 1][lr] = w4.y;
        Bs[lc + 2][lr] = w4.z; Bs[lc + 3][lr] = w4.w;
        __syncthreads();

#pragma unroll
        for (int k = 0; k < 8; k++) {
            float av[8];
            F4U2 B0, B1;
            *(float4*)&av[0] = *(const float4*)&As[k][ty * 8];
            *(float4*)&av[4] = *(const float4*)&As[k][ty * 8 + 4];
            B0.f4 = *(const float4*)&Bs[k][tx * 8];
            B1.f4 = *(const float4*)&Bs[k][tx * 8 + 4];
            const u64cu bp0 = B0.u2[0], bp1 = B0.u2[1];
            const u64cu bp2 = B1.u2[0], bp3 = B1.u2[1];
#pragma unroll
            for (int i = 0; i < 8; i++) {
                const u64cu ai = dup2(av[i]);
                fma2(accp[i][0], ai, bp0);
                fma2(accp[i][1], ai, bp1);
                fma2(accp[i][2], ai, bp2);
                fma2(accp[i][3], ai, bp3);
            }
        }
        __syncthreads();
    }

    const int b  = (bi + ty * 8) >> 11;     // 8-row strip never crosses b
    const int s0 = (bi + ty * 8) & 2047;

    if (z == 0) {
        // Q: head-split [b,h][s][d], float2 pairs.
#pragma unroll
        for (int ii = 0; ii < 8; ii++) {
            const int s = s0 + ii;
#pragma unroll
            for (int p = 0; p < 4; p++) {
                const int j = bj + tx * 8 + 2 * p;
                const int h = j >> 6;
                const int d = j & 63;
                float2 v = up2(accp[ii][p]);
                v.x += bias[j];
                v.y += bias[j + 1];
                *(float2*)&dst[(((size_t)(b * HH + h)) * SS + s) * HD + d] = v;
            }
        }
    } else {
        // K transposed: [b,h][d][s]; per col j, 8 consecutive s -> 2x float4.
#pragma unroll
        for (int p = 0; p < 4; p++) {
            const int j = bj + tx * 8 + 2 * p;
            float v0[8], v1[8];
#pragma unroll
            for (int ii = 0; ii < 8; ii++) {
                float2 v = up2(accp[ii][p]);
                v0[ii] = v.x + bias[j];
                v1[ii] = v.y + bias[j + 1];
            }
            const int h0 = j >> 6, d0 = j & 63;
            const int h1 = (j + 1) >> 6, d1 = (j + 1) & 63;
            float* p0 = &dst[(((size_t)(b * HH + h0)) * HD + d0) * SS + s0];
            float* p1 = &dst[(((size_t)(b * HH + h1)) * HD + d1) * SS + s0];
            *(float4*)p0       = *(float4*)&v0[0];
            *(float4*)(p0 + 4) = *(float4*)&v0[4];
            *(float4*)p1       = *(float4*)&v1[0];
            *(float4*)(p1 + 4) = *(float4*)&v1[4];
        }
    }
}

// ---------------------------------------------------------------------------
// V projection via 3xTF32 mma.sync (terminal path; tf32 noise harmless).
// ---------------------------------------------------------------------------
#define PJ_STR 36
#define PROJ_SMEM (4 * 128 * PJ_STR * 4)

__global__ void __launch_bounds__(256, 2)
proj_v_mma(const float* __restrict__ X, const float* __restrict__ W,
           const float* __restrict__ bias)
{
    extern __shared__ float ps[];
    float* sXh = ps;
    float* sXl = ps + 128 * PJ_STR;
    float* sWh = ps + 2 * 128 * PJ_STR;
    float* sWl = ps + 3 * 128 * PJ_STR;
    float* dst = g_V;

    const int bi = blockIdx.y * 128;
    const int bj = blockIdx.x * 128;
    const int tid  = threadIdx.x;
    const int wid  = tid >> 5;
    const int lane = tid & 31;
    const int wm = wid >> 2;
    const int wn = wid & 3;
    const int lr = lane >> 2;
    const int lc = lane & 3;

    float c[4][4][4];
#pragma unroll
    for (int i = 0; i < 4; i++)
#pragma unroll
        for (int j = 0; j < 4; j++)
#pragma unroll
            for (int e = 0; e < 4; e++) c[i][j][e] = 0.0f;

    for (int ch = 0; ch < 32; ch++) {
        const int k0 = ch * 32;
#pragma unroll
        for (int it = 0; it < 4; it++) {
            const int idx = tid + it * 256;
            const int row = idx >> 3;
            const int q   = (idx & 7) * 4;
            float4 xv = *(const float4*)&X[(size_t)(bi + row) * DD + k0 + q];
            float4 wv = *(const float4*)&W[(size_t)(bj + row) * DD + k0 + q];
            float xh[4], xl[4], wh[4], wl[4];
            const float* xs = (const float*)&xv;
            const float* ws = (const float*)&wv;
#pragma unroll
            for (int e = 0; e < 4; e++) {
                split_tf32(xs[e], xh[e], xl[e]);
                split_tf32(ws[e], wh[e], wl[e]);
            }
            *(float4*)&sXh[row * PJ_STR + q] = *(float4*)xh;
            *(float4*)&sXl[row * PJ_STR + q] = *(float4*)xl;
            *(float4*)&sWh[row * PJ_STR + q] = *(float4*)wh;
            *(float4*)&sWl[row * PJ_STR + q] = *(float4*)wl;
        }
        __syncthreads();

#pragma unroll
        for (int k8 = 0; k8 < 4; k8++) {
            const int kc = k8 * 8;
            uint32_t bh[4][2], bl[4][2];
#pragma unroll
            for (int nt = 0; nt < 4; nt++) {
                const int nr = (wn * 32 + nt * 8 + lr) * PJ_STR + kc + lc;
                bh[nt][0] = __float_as_uint(sWh[nr]);
                bh[nt][1] = __float_as_uint(sWh[nr + 4]);
                bl[nt][0] = __float_as_uint(sWl[nr]);
                bl[nt][1] = __float_as_uint(sWl[nr + 4]);
            }
#pragma unroll
            for (int mt = 0; mt < 4; mt++) {
                const int ar = (wm * 64 + mt * 16 + lr) * PJ_STR + kc + lc;
                uint32_t ah[4], al[4];
                ah[0] = __float_as_uint(sXh[ar]);
                ah[1] = __float_as_uint(sXh[ar + 8 * PJ_STR]);
                ah[2] = __float_as_uint(sXh[ar + 4]);
                ah[3] = __float_as_uint(sXh[ar + 8 * PJ_STR + 4]);
                al[0] = __float_as_uint(sXl[ar]);
                al[1] = __float_as_uint(sXl[ar + 8 * PJ_STR]);
                al[2] = __float_as_uint(sXl[ar + 4]);
                al[3] = __float_as_uint(sXl[ar + 8 * PJ_STR + 4]);
#pragma unroll
                for (int nt = 0; nt < 4; nt++) {
                    mma8(c[mt][nt], ah, bh[nt]);   // hi*hi
                    mma8(c[mt][nt], ah, bl[nt]);   // hi*lo
                    mma8(c[mt][nt], al, bh[nt]);   // lo*hi
                }
            }
        }
        __syncthreads();
    }

#pragma unroll
    for (int mt = 0; mt < 4; mt++) {
        const int i0 = bi + wm * 64 + mt * 16 + lr;
#pragma unroll
        for (int nt = 0; nt < 4; nt++) {
            const int j = bj + wn * 32 + nt * 8 + 2 * lc;
            const float b0 = bias[j], b1 = bias[j + 1];
            const int h = j >> 6;
            const int d = j & 63;
            {
                const int bb = i0 >> 11, s = i0 & 2047;
                float2 v = make_float2(c[mt][nt][0] + b0, c[mt][nt][1] + b1);
                *(float2*)&dst[(((size_t)(bb * HH + h)) * SS + s) * HD + d] = v;
            }
            {
                const int i1 = i0 + 8;
                const int bb = i1 >> 11, s = i1 & 2047;
                float2 v = make_float2(c[mt][nt][2] + b0, c[mt][nt][3] + b1);
                *(float2*)&dst[(((size_t)(bb * HH + h)) * SS + s) * HD + d] = v;
            }
        }
    }
}

// ---------------------------------------------------------------------------
// Fused attention per (b, h, 16-row q-block). 512 threads (16 warps).
//   Phase 1: fp32 QK^T, ROUND-7 ARITHMETIC VERBATIM (bit-identical raw);
//            only change: K pre-transposed -> coalesced copy, no swizzle.
//   Phase 2: softmax, one warp per row.
//   Phase 3: attn_mean += attn/H via red.global.add.v4.f32.
//   Phase 4: attn @ V via single-TF32 mma.sync; 16-way k-split by warp.
// ---------------------------------------------------------------------------
#define SC_STR 2052
#define SMEM_FLOATS (16 * SC_STR + 17408 + 1024)
#define SMEM_BYTES  (SMEM_FLOATS * 4)

__global__ void __launch_bounds__(512) attn_kernel(float* __restrict__ out)
{
    extern __shared__ float sm[];
    float* sc  = sm;                      // scores / attn, [16][2052]
    float* kv  = sm + 16 * SC_STR;        // K^T chunk [64][256] / V [256][68] / red
    float* qt  = sm + 16 * SC_STR + 17408;// Q^T [64][16]

    const int cta = blockIdx.x;
    const int qb  = cta & 127;
    const int h   = (cta >> 7) & 15;
    const int b   = cta >> 11;
    const int q0  = qb * 16;
    const int tid = threadIdx.x;
    const int wid  = tid >> 5;
    const int lane = tid & 31;

    const float* Qg = g_Q + ((size_t)(b * HH + h) * SS + q0) * HD;
    const float* Kg = g_K + (size_t)(b * HH + h) * HD * SS;   // [d][s]
    const float* Vg = g_V + (size_t)(b * HH + h) * SS * HD;

    if (tid < 256) {
        const int r  = tid >> 4;
        const int c4 = (tid & 15) * 4;
        float4 v = *(const float4*)&Qg[r * HD + c4];
        qt[(c4 + 0) * 16 + r] = v.x;
        qt[(c4 + 1) * 16 + r] = v.y;
        qt[(c4 + 2) * 16 + r] = v.z;
        qt[(c4 + 3) * 16 + r] = v.w;
    }

    // ---- Phase 1: scores = 1 / (8 * Q K^T), fp32 (round-7 order) ----
    const int rg  = tid >> 7;
    const int cg  = tid & 127;
    const int r0  = rg * 4;
    const int cg2 = cg * 2;

    for (int kc = 0; kc < 8; kc++) {
        // K^T chunk [64 d][256 s]: straight coalesced float4 copy.
#pragma unroll
        for (int i = 0; i < 8; i++) {
            const int f  = tid + i * 512;
            const int d  = f >> 6;
            const int c4 = (f & 63) * 4;
            float4 v = *(const float4*)(Kg + (size_t)d * SS + kc * 256 + c4);
            *(float4*)&kv[d * 256 + c4] = v;
        }
        __syncthreads();

        // Round-7 accumulators: row pairs (r0,r0+1),(r0+2,r0+3) x 2 cols.
        u64cu a01c0 = 0ULL, a23c0 = 0ULL, a01c1 = 0ULL, a23c1 = 0ULL;

#pragma unroll 8
        for (int d = 0; d < 64; d++) {
            F4U2 qv;
            qv.f4 = *(const float4*)&qt[d * 16 + r0];      // broadcast
            const u64cu q01 = qv.u2[0], q23 = qv.u2[1];
            float2 kvv = *(const float2*)&kv[d * 256 + cg2];
            const u64cu k0d = dup2(kvv.x);
            const u64cu k1d = dup2(kvv.y);
            fma2(a01c0, q01, k0d);
            fma2(a23c0, q23, k0d);
            fma2(a01c1, q01, k1d);
            fma2(a23c1, q23, k1d);
        }

        {
            float2 c0lo = up2(a01c0), c0hi = up2(a23c0);
            float2 c1lo = up2(a01c1), c1hi = up2(a23c1);
            float rowv[4][2] = {{c0lo.x, c1lo.x}, {c0lo.y, c1lo.y},
                                {c0hi.x, c1hi.x}, {c0hi.y, c1hi.y}};
#pragma unroll
            for (int i = 0; i < 4; i++) {
                float2 sv;
                sv.x = __fdividef(1.0f, 8.0f * rowv[i][0]);
                sv.y = __fdividef(1.0f, 8.0f * rowv[i][1]);
                *(float2*)&sc[(r0 + i) * SC_STR + kc * 256 + cg2] = sv;
            }
        }
        __syncthreads();
    }

    // ---- Phase 2: softmax per row (one warp per row) ----
    {
        float* row = sc + wid * SC_STR;
        float m = -3.4e38f;
        for (int k = lane; k < 2048; k += 32) m = fmaxf(m, row[k]);
#pragma unroll
        for (int o = 16; o; o >>= 1) m = fmaxf(m, __shfl_xor_sync(0xffffffffu, m, o));
        float ssum = 0.0f;
        for (int k = lane; k < 2048; k += 32) {
            float e = __expf(row[k] - m);
            row[k] = e;
            ssum += e;
        }
#pragma unroll
        for (int o = 16; o; o >>= 1) ssum += __shfl_xor_sync(0xffffffffu, ssum, o);
        const float inv = __fdividef(1.0f, ssum);
        for (int k = lane; k < 2048; k += 32) row[k] *= inv;
    }
    __syncthreads();

    // ---- Phase 3: attn_mean += attn / H ----
    {
        float* am = out + (size_t)BB * SS * DD;
        for (int idx4 = tid; idx4 < 8192; idx4 += 512) {
            const int rr = idx4 >> 9;
            const int kk = (idx4 & 511) * 4;
            float4 v = *(const float4*)&sc[rr * SC_STR + kk];
            v.x *= 0.0625f; v.y *= 0.0625f; v.z *= 0.0625f; v.w *= 0.0625f;
            float* p = &am[((size_t)(b * SS + q0 + rr)) * SS + kk];
            asm volatile("red.global.add.v4.f32 [%0], {%1, %2, %3, %4};"
                         :: "l"(p), "f"(v.x), "f"(v.y), "f"(v.z), "f"(v.w)
                         : "memory");
        }
    }

    // ---- Phase 4: out = attn @ V via tf32 mma (16-way k-split by warp) ----
    {
        const int lr = lane >> 2;
        const int lc = lane & 3;

        float c[8][4];
#pragma unroll
        for (int nt = 0; nt < 8; nt++)
#pragma unroll
            for (int e = 0; e < 4; e++) c[nt][e] = 0.0f;

        for (int vc = 0; vc < 8; vc++) {
            const float4* Vc4 = (const float4*)(Vg + (size_t)vc * 256 * HD);
#pragma unroll
            for (int i = 0; i < 8; i++) {
                const int f   = tid + i * 512;
                const int row = f >> 4;
                const int nq  = (f & 15) * 4;
                *(float4*)&kv[row * 68 + nq] = Vc4[f];
            }
            __syncthreads();

#pragma unroll
            for (int t = 0; t < 2; t++) {
                const int kc = (wid * 2 + t) * 8;
                uint32_t a[4];
                const int ac = vc * 256 + kc + lc;
                a[0] = f2tf32(sc[lr * SC_STR + ac]);
                a[1] = f2tf32(sc[(lr + 8) * SC_STR + ac]);
                a[2] = f2tf32(sc[lr * SC_STR + ac + 4]);
                a[3] = f2tf32(sc[(lr + 8) * SC_STR + ac + 4]);
#pragma unroll
                for (int nt = 0; nt < 8; nt++) {
                    uint32_t bf[2];
                    const int n = nt * 8 + lr;
                    bf[0] = f2tf32(kv[(kc + lc) * 68 + n]);
                    bf[1] = f2tf32(kv[(kc + lc + 4) * 68 + n]);
                    mma8(c[nt], a, bf);
                }
            }
            __syncthreads();
        }

        float* red = kv;
#pragma unroll
        for (int nt = 0; nt < 8; nt++) {
            const int col = nt * 8 + 2 * lc;
            red[wid * 1024 + lr * 64 + col]           = c[nt][0];
            red[wid * 1024 + lr * 64 + col + 1]       = c[nt][1];
            red[wid * 1024 + (lr + 8) * 64 + col]     = c[nt][2];
            red[wid * 1024 + (lr + 8) * 64 + col + 1] = c[nt][3];
        }
        __syncthreads();

        for (int e = tid; e < 1024; e += 512) {
            const int r = e >> 6;
            const int d = e & 63;
            float v = 0.0f;
#pragma unroll
            for (int g = 0; g < 16; g++) v += red[g * 1024 + e];
            out[((size_t)(b * SS + q0 + r)) * DD + h * HD + d] = v;
        }
    }
}

// ---------------------------------------------------------------------------
extern "C" void kernel_launch(void* const* d_in, const int* in_sizes, int n_in,
                              void* d_out, int out_size)
{
    const float* query = (const float*)d_in[0];
    const float* key_  = (const float*)d_in[1];
    const float* value = (const float*)d_in[2];
    const float* Wq    = (const float*)d_in[3];
    const float* bq    = (const float*)d_in[4];
    const float* Wk    = (const float*)d_in[5];
    const float* bk    = (const float*)d_in[6];
    const float* Wv    = (const float*)d_in[7];
    const float* bv    = (const float*)d_in[8];
    float* out = (float*)d_out;

    cudaMemsetAsync(out + (size_t)BB * SS * DD, 0,
                    (size_t)BB * SS * SS * sizeof(float));

    // Q,K: fp32 (precision-critical; K stored transposed). V: 3xTF32 tensor.
    dim3 pg(DD / 128, (BB * SS) / 128, 2);
    proj_qk<<<pg, 256>>>(query, key_, Wq, Wk, bq, bk);

    cudaFuncSetAttribute(proj_v_mma,
                         cudaFuncAttributeMaxDynamicSharedMemorySize, PROJ_SMEM);
    dim3 pv(DD / 128, (BB * SS) / 128);
    proj_v_mma<<<pv, 256, PROJ_SMEM>>>(value, Wv, bv);

    cudaFuncSetAttribute(attn_kernel,
                         cudaFuncAttributeMaxDynamicSharedMemorySize, SMEM_BYTES);
    attn_kernel<<<BB * HH * (SS / 16), 512, SMEM_BYTES>>>(out);
}

// round 11
// speedup vs baseline: 1.7885x; 1.0460x over previous
#include <cuda_runtime.h>
#include <cstdint>

#define BB 2
#define SS 2048
#define DD 1024
#define HH 16
#define HD 64

// Scratch: g_Q [b,h][s][64]; g_K TRANSPOSED [b,h][d][s]; g_V [b,h][s][64].
__device__ float g_Q[BB*HH*SS*HD];
__device__ float g_K[BB*HH*SS*HD];
__device__ float g_V[BB*HH*SS*HD];

// ---------------------------------------------------------------------------
// Packed f32x2 helpers (exact IEEE fp32 per lane).
// ---------------------------------------------------------------------------
typedef unsigned long long u64cu;
union F4U2 { float4 f4; u64cu u2[2]; };

__device__ __forceinline__ u64cu dup2(float x) {
    u64cu r; asm("mov.b64 %0, {%1, %1};" : "=l"(r) : "f"(x)); return r;
}
__device__ __forceinline__ void fma2(u64cu& c, u64cu a, u64cu b) {
    asm("fma.rn.f32x2 %0, %1, %2, %0;" : "+l"(c) : "l"(a), "l"(b));
}
__device__ __forceinline__ float2 up2(u64cu v) {
    float2 f; asm("mov.b64 {%0, %1}, %2;" : "=f"(f.x), "=f"(f.y) : "l"(v));
    return f;
}

// ---------------------------------------------------------------------------
// tf32 mma.sync helpers (downstream-of-softmax paths only).
// ---------------------------------------------------------------------------
__device__ __forceinline__ uint32_t f2tf32(float x) {
    uint32_t r;
    asm("cvt.rna.tf32.f32 %0, %1;" : "=r"(r) : "f"(x));
    return r;
}
__device__ __forceinline__ void split_tf32(float v, float& hi, float& lo) {
    uint32_t hb;
    asm("cvt.rna.tf32.f32 %0, %1;" : "=r"(hb) : "f"(v));
    hi = __uint_as_float(hb);
    float r = v - hi;
    uint32_t lb;
    asm("cvt.rna.tf32.f32 %0, %1;" : "=r"(lb) : "f"(r));
    lo = __uint_as_float(lb);
}
__device__ __forceinline__ void mma8(float* c, const uint32_t* a, const uint32_t* bf) {
    asm volatile("mma.sync.aligned.m16n8k8.row.col.f32.tf32.tf32.f32 "
                 "{%0,%1,%2,%3}, {%4,%5,%6,%7}, {%8,%9}, {%0,%1,%2,%3};"
                 : "+f"(c[0]), "+f"(c[1]), "+f"(c[2]), "+f"(c[3])
                 : "r"(a[0]), "r"(a[1]), "r"(a[2]), "r"(a[3]),
                   "r"(bf[0]), "r"(bf[1]));
}

// ---------------------------------------------------------------------------
// ALL projections in ONE launch, grid (8, 32, 3):
//   z=0 -> Q fp32 SIMT (head-split [b,h][s][d])   — precision-critical
//   z=1 -> K fp32 SIMT (TRANSPOSED [b,h][d][s])   — precision-critical
//   z=2 -> V 3xTF32 mma.sync (terminal path)      — tensor pipe
// Concurrent z-planes overlap FMA (Q/K) with tensor+L1 (V) chip-wide.
// Dynamic smem 73728 B shared by both paths.
// ---------------------------------------------------------------------------
#define PJ_STR 36
#define PROJ_SMEM (4 * 128 * PJ_STR * 4)

__global__ void __launch_bounds__(256, 2)
proj_all(const float* __restrict__ Xq, const float* __restrict__ Xk,
         const float* __restrict__ Xv,
         const float* __restrict__ Wq, const float* __restrict__ Wk,
         const float* __restrict__ Wv,
         const float* __restrict__ bq, const float* __restrict__ bk,
         const float* __restrict__ bv)
{
    extern __shared__ float ps[];
    const int z   = blockIdx.z;
    const int bi  = blockIdx.y * 128;
    const int bj  = blockIdx.x * 128;
    const int tid = threadIdx.x;

    if (z < 2) {
        // ================= Q/K: fp32 SIMT (f32x2), bit-exact path ==========
        const float* X    = z ? Xk : Xq;
        const float* W    = z ? Wk : Wq;
        const float* bias = z ? bk : bq;
        float* dst        = z ? g_K : g_Q;

        float* As = ps;             // [8][128]
        float* Bs = ps + 8 * 128;   // [8][128]

        const int tx = tid & 15;
        const int ty = tid >> 4;
        const int lr = tid >> 1;
        const int lc = (tid & 1) * 4;

        const float* Xp = X + (size_t)(bi + lr) * DD + lc;
        const float* Wp = W + (size_t)(bj + lr) * DD + lc;

        u64cu accp[8][4];
#pragma unroll
        for (int i = 0; i < 8; i++)
#pragma unroll
            for (int p = 0; p < 4; p++) accp[i][p] = 0ULL;

        for (int k0 = 0; k0 < DD; k0 += 8) {
            float4 a4 = *(const float4*)(Xp + k0);
            float4 w4 = *(const float4*)(Wp + k0);
            As[(lc + 0) * 128 + lr] = a4.x; As[(lc + 1) * 128 + lr] = a4.y;
            As[(lc + 2) * 128 + lr] = a4.z; As[(lc + 3) * 128 + lr] = a4.w;
            Bs[(lc + 0) * 128 + lr] = w4.x; Bs[(lc + 1) * 128 + lr] = w4.y;
            Bs[(lc + 2) * 128 + lr] = w4.z; Bs[(lc + 3) * 128 + lr] = w4.w;
            __syncthreads();

#pragma unroll
            for (int k = 0; k < 8; k++) {
                float av[8];
                F4U2 B0, B1;
                *(float4*)&av[0] = *(const float4*)&As[k * 128 + ty * 8];
                *(float4*)&av[4] = *(const float4*)&As[k * 128 + ty * 8 + 4];
                B0.f4 = *(const float4*)&Bs[k * 128 + tx * 8];
                B1.f4 = *(const float4*)&Bs[k * 128 + tx * 8 + 4];
                const u64cu bp0 = B0.u2[0], bp1 = B0.u2[1];
                const u64cu bp2 = B1.u2[0], bp3 = B1.u2[1];
#pragma unroll
                for (int i = 0; i < 8; i++) {
                    const u64cu ai = dup2(av[i]);
                    fma2(accp[i][0], ai, bp0);
                    fma2(accp[i][1], ai, bp1);
                    fma2(accp[i][2], ai, bp2);
                    fma2(accp[i][3], ai, bp3);
                }
            }
            __syncthreads();
        }

        const int b  = (bi + ty * 8) >> 11;
        const int s0 = (bi + ty * 8) & 2047;

        if (z == 0) {
#pragma unroll
            for (int ii = 0; ii < 8; ii++) {
                const int s = s0 + ii;
#pragma unroll
                for (int p = 0; p < 4; p++) {
                    const int j = bj + tx * 8 + 2 * p;
                    const int h = j >> 6;
                    const int d = j & 63;
                    float2 v = up2(accp[ii][p]);
                    v.x += bias[j];
                    v.y += bias[j + 1];
                    *(float2*)&dst[(((size_t)(b * HH + h)) * SS + s) * HD + d] = v;
                }
            }
        } else {
#pragma unroll
            for (int p = 0; p < 4; p++) {
                const int j = bj + tx * 8 + 2 * p;
                float v0[8], v1[8];
#pragma unroll
                for (int ii = 0; ii < 8; ii++) {
                    float2 v = up2(accp[ii][p]);
                    v0[ii] = v.x + bias[j];
                    v1[ii] = v.y + bias[j + 1];
                }
                const int h0 = j >> 6, d0 = j & 63;
                const int h1 = (j + 1) >> 6, d1 = (j + 1) & 63;
                float* p0 = &dst[(((size_t)(b * HH + h0)) * HD + d0) * SS + s0];
                float* p1 = &dst[(((size_t)(b * HH + h1)) * HD + d1) * SS + s0];
                *(float4*)p0       = *(float4*)&v0[0];
                *(float4*)(p0 + 4) = *(float4*)&v0[4];
                *(float4*)p1       = *(float4*)&v1[0];
                *(float4*)(p1 + 4) = *(float4*)&v1[4];
            }
        }
        return;
    }

    // ================= V: 3xTF32 mma.sync (terminal path) ===================
    {
        const float* X    = Xv;
        const float* W    = Wv;
        const float* bias = bv;
        float* dst        = g_V;

        float* sXh = ps;
        float* sXl = ps + 128 * PJ_STR;
        float* sWh = ps + 2 * 128 * PJ_STR;
        float* sWl = ps + 3 * 128 * PJ_STR;

        const int wid  = tid >> 5;
        const int lane = tid & 31;
        const int wm = wid >> 2;
        const int wn = wid & 3;
        const int lr = lane >> 2;
        const int lc = lane & 3;

        float c[4][4][4];
#pragma unroll
        for (int i = 0; i < 4; i++)
#pragma unroll
            for (int j = 0; j < 4; j++)
#pragma unroll
                for (int e = 0; e < 4; e++) c[i][j][e] = 0.0f;

        for (int ch = 0; ch < 32; ch++) {
            const int k0 = ch * 32;
#pragma unroll
            for (int it = 0; it < 4; it++) {
                const int idx = tid + it * 256;
                const int row = idx >> 3;
                const int q   = (idx & 7) * 4;
                float4 xv = *(const float4*)&X[(size_t)(bi + row) * DD + k0 + q];
                float4 wv = *(const float4*)&W[(size_t)(bj + row) * DD + k0 + q];
                float xh[4], xl[4], wh[4], wl[4];
                const float* xs = (const float*)&xv;
                const float* ws = (const float*)&wv;
#pragma unroll
                for (int e = 0; e < 4; e++) {
                    split_tf32(xs[e], xh[e], xl[e]);
                    split_tf32(ws[e], wh[e], wl[e]);
                }
                *(float4*)&sXh[row * PJ_STR + q] = *(float4*)xh;
                *(float4*)&sXl[row * PJ_STR + q] = *(float4*)xl;
                *(float4*)&sWh[row * PJ_STR + q] = *(float4*)wh;
                *(float4*)&sWl[row * PJ_STR + q] = *(float4*)wl;
            }
            __syncthreads();

#pragma unroll
            for (int k8 = 0; k8 < 4; k8++) {
                const int kc = k8 * 8;
                uint32_t bh[4][2], bl[4][2];
#pragma unroll
                for (int nt = 0; nt < 4; nt++) {
                    const int nr = (wn * 32 + nt * 8 + lr) * PJ_STR + kc + lc;
                    bh[nt][0] = __float_as_uint(sWh[nr]);
                    bh[nt][1] = __float_as_uint(sWh[nr + 4]);
                    bl[nt][0] = __float_as_uint(sWl[nr]);
                    bl[nt][1] = __float_as_uint(sWl[nr + 4]);
                }
#pragma unroll
                for (int mt = 0; mt < 4; mt++) {
                    const int ar = (wm * 64 + mt * 16 + lr) * PJ_STR + kc + lc;
                    uint32_t ah[4], al[4];
                    ah[0] = __float_as_uint(sXh[ar]);
                    ah[1] = __float_as_uint(sXh[ar + 8 * PJ_STR]);
                    ah[2] = __float_as_uint(sXh[ar + 4]);
                    ah[3] = __float_as_uint(sXh[ar + 8 * PJ_STR + 4]);
                    al[0] = __float_as_uint(sXl[ar]);
                    al[1] = __float_as_uint(sXl[ar + 8 * PJ_STR]);
                    al[2] = __float_as_uint(sXl[ar + 4]);
                    al[3] = __float_as_uint(sXl[ar + 8 * PJ_STR + 4]);
#pragma unroll
                    for (int nt = 0; nt < 4; nt++) {
                        mma8(c[mt][nt], ah, bh[nt]);   // hi*hi
                        mma8(c[mt][nt], ah, bl[nt]);   // hi*lo
                        mma8(c[mt][nt], al, bh[nt]);   // lo*hi
                    }
                }
            }
            __syncthreads();
        }

#pragma unroll
        for (int mt = 0; mt < 4; mt++) {
            const int i0 = bi + wm * 64 + mt * 16 + lr;
#pragma unroll
            for (int nt = 0; nt < 4; nt++) {
                const int j = bj + wn * 32 + nt * 8 + 2 * lc;
                const float b0 = bias[j], b1 = bias[j + 1];
                const int h = j >> 6;
                const int d = j & 63;
                {
                    const int bb = i0 >> 11, s = i0 & 2047;
                    float2 v = make_float2(c[mt][nt][0] + b0, c[mt][nt][1] + b1);
                    *(float2*)&dst[(((size_t)(bb * HH + h)) * SS + s) * HD + d] = v;
                }
                {
                    const int i1 = i0 + 8;
                    const int bb = i1 >> 11, s = i1 & 2047;
                    float2 v = make_float2(c[mt][nt][2] + b0, c[mt][nt][3] + b1);
                    *(float2*)&dst[(((size_t)(bb * HH + h)) * SS + s) * HD + d] = v;
                }
            }
        }
    }
}

// ---------------------------------------------------------------------------
// Fused attention per (b, h, 16-row q-block). 512 threads (16 warps).
//   Phase 1: fp32 QK^T (round-7 arithmetic, bit-identical raw).
//   Phase 2: softmax + FUSED attn_mean reduction (red.v4 in normalize pass).
//   Phase 3: attn @ V via single-TF32 mma.sync; partials go straight to out
//            via red.global.add.v2 (out pre-zeroed; no smem reduction).
// ---------------------------------------------------------------------------
#define SC_STR 2052
#define SMEM_FLOATS (16 * SC_STR + 17408 + 1024)
#define SMEM_BYTES  (SMEM_FLOATS * 4)

__global__ void __launch_bounds__(512) attn_kernel(float* __restrict__ out)
{
    extern __shared__ float sm[];
    float* sc  = sm;                      // scores / attn, [16][2052]
    float* kv  = sm + 16 * SC_STR;        // K^T chunk [64][256] / V [256][68]
    float* qt  = sm + 16 * SC_STR + 17408;// Q^T [64][16]

    const int cta = blockIdx.x;
    const int qb  = cta & 127;
    const int h   = (cta >> 7) & 15;
    const int b   = cta >> 11;
    const int q0  = qb * 16;
    const int tid = threadIdx.x;
    const int wid  = tid >> 5;
    const int lane = tid & 31;

    const float* Qg = g_Q + ((size_t)(b * HH + h) * SS + q0) * HD;
    const float* Kg = g_K + (size_t)(b * HH + h) * HD * SS;   // [d][s]
    const float* Vg = g_V + (size_t)(b * HH + h) * SS * HD;

    if (tid < 256) {
        const int r  = tid >> 4;
        const int c4 = (tid & 15) * 4;
        float4 v = *(const float4*)&Qg[r * HD + c4];
        qt[(c4 + 0) * 16 + r] = v.x;
        qt[(c4 + 1) * 16 + r] = v.y;
        qt[(c4 + 2) * 16 + r] = v.z;
        qt[(c4 + 3) * 16 + r] = v.w;
    }

    // ---- Phase 1: scores = 1 / (8 * Q K^T), fp32 (round-7 order) ----
    const int rg  = tid >> 7;
    const int cg  = tid & 127;
    const int r0  = rg * 4;
    const int cg2 = cg * 2;

    for (int kc = 0; kc < 8; kc++) {
#pragma unroll
        for (int i = 0; i < 8; i++) {
            const int f  = tid + i * 512;
            const int d  = f >> 6;
            const int c4 = (f & 63) * 4;
            float4 v = *(const float4*)(Kg + (size_t)d * SS + kc * 256 + c4);
            *(float4*)&kv[d * 256 + c4] = v;
        }
        __syncthreads();

        u64cu a01c0 = 0ULL, a23c0 = 0ULL, a01c1 = 0ULL, a23c1 = 0ULL;

#pragma unroll 8
        for (int d = 0; d < 64; d++) {
            F4U2 qv;
            qv.f4 = *(const float4*)&qt[d * 16 + r0];      // broadcast
            const u64cu q01 = qv.u2[0], q23 = qv.u2[1];
            float2 kvv = *(const float2*)&kv[d * 256 + cg2];
            const u64cu k0d = dup2(kvv.x);
            const u64cu k1d = dup2(kvv.y);
            fma2(a01c0, q01, k0d);
            fma2(a23c0, q23, k0d);
            fma2(a01c1, q01, k1d);
            fma2(a23c1, q23, k1d);
        }

        {
            float2 c0lo = up2(a01c0), c0hi = up2(a23c0);
            float2 c1lo = up2(a01c1), c1hi = up2(a23c1);
            float rowv[4][2] = {{c0lo.x, c1lo.x}, {c0lo.y, c1lo.y},
                                {c0hi.x, c1hi.x}, {c0hi.y, c1hi.y}};
#pragma unroll
            for (int i = 0; i < 4; i++) {
                float2 sv;
                sv.x = __fdividef(1.0f, 8.0f * rowv[i][0]);
                sv.y = __fdividef(1.0f, 8.0f * rowv[i][1]);
                *(float2*)&sc[(r0 + i) * SC_STR + kc * 256 + cg2] = sv;
            }
        }
        __syncthreads();
    }

    // ---- Phase 2: softmax per row + fused attn_mean red.v4 ----
    {
        float* row = sc + wid * SC_STR;
        float m = -3.4e38f;
        for (int k = lane; k < 2048; k += 32) m = fmaxf(m, row[k]);
#pragma unroll
        for (int o = 16; o; o >>= 1) m = fmaxf(m, __shfl_xor_sync(0xffffffffu, m, o));
        float ssum = 0.0f;
        for (int k = lane; k < 2048; k += 32) {
            float e = __expf(row[k] - m);
            row[k] = e;
            ssum += e;
        }
#pragma unroll
        for (int o = 16; o; o >>= 1) ssum += __shfl_xor_sync(0xffffffffu, ssum, o);
        const float inv = __fdividef(1.0f, ssum);

        float* am = out + (size_t)BB * SS * DD
                  + ((size_t)(b * SS + q0 + wid)) * SS;
        for (int k4 = lane * 4; k4 < 2048; k4 += 128) {
            float4 v = *(const float4*)&row[k4];
            v.x *= inv; v.y *= inv; v.z *= inv; v.w *= inv;
            *(float4*)&row[k4] = v;
            float4 vm = make_float4(v.x * 0.0625f, v.y * 0.0625f,
                                    v.z * 0.0625f, v.w * 0.0625f);
            asm volatile("red.global.add.v4.f32 [%0], {%1, %2, %3, %4};"
                         :: "l"(am + k4), "f"(vm.x), "f"(vm.y), "f"(vm.z), "f"(vm.w)
                         : "memory");
        }
    }
    __syncthreads();

    // ---- Phase 3: out += attn @ V via tf32 mma (16-way k-split by warp),
    //      partials accumulated directly with red.global.add.v2 ----
    {
        const int lr = lane >> 2;
        const int lc = lane & 3;

        float c[8][4];
#pragma unroll
        for (int nt = 0; nt < 8; nt++)
#pragma unroll
            for (int e = 0; e < 4; e++) c[nt][e] = 0.0f;

        for (int vc = 0; vc < 8; vc++) {
            const float4* Vc4 = (const float4*)(Vg + (size_t)vc * 256 * HD);
#pragma unroll
            for (int i = 0; i < 8; i++) {
                const int f   = tid + i * 512;
                const int row = f >> 4;
                const int nq  = (f & 15) * 4;
                *(float4*)&kv[row * 68 + nq] = Vc4[f];
            }
            __syncthreads();

#pragma unroll
            for (int t = 0; t < 2; t++) {
                const int kc = (wid * 2 + t) * 8;
                uint32_t a[4];
                const int ac = vc * 256 + kc + lc;
                a[0] = f2tf32(sc[lr * SC_STR + ac]);
                a[1] = f2tf32(sc[(lr + 8) * SC_STR + ac]);
                a[2] = f2tf32(sc[lr * SC_STR + ac + 4]);
                a[3] = f2tf32(sc[(lr + 8) * SC_STR + ac + 4]);
#pragma unroll
                for (int nt = 0; nt < 8; nt++) {
                    uint32_t bf[2];
                    const int n = nt * 8 + lr;
                    bf[0] = f2tf32(kv[(kc + lc) * 68 + n]);
                    bf[1] = f2tf32(kv[(kc + lc + 4) * 68 + n]);
                    mma8(c[nt], a, bf);
                }
            }
            __syncthreads();
        }

        // Direct atomic accumulation of the 16 k-split partials into out.
        float* ob = out + ((size_t)(b * SS + q0)) * DD + h * HD;
#pragma unroll
        for (int nt = 0; nt < 8; nt++) {
            const int col = nt * 8 + 2 * lc;
            float* p0 = ob + (size_t)lr * DD + col;
            float* p1 = ob + (size_t)(lr + 8) * DD + col;
            asm volatile("red.global.add.v2.f32 [%0], {%1, %2};"
                         :: "l"(p0), "f"(c[nt][0]), "f"(c[nt][1]) : "memory");
            asm volatile("red.global.add.v2.f32 [%0], {%1, %2};"
                         :: "l"(p1), "f"(c[nt][2]), "f"(c[nt][3]) : "memory");
        }
    }
}

// ---------------------------------------------------------------------------
extern "C" void kernel_launch(void* const* d_in, const int* in_sizes, int n_in,
                              void* d_out, int out_size)
{
    const float* query = (const float*)d_in[0];
    const float* key_  = (const float*)d_in[1];
    const float* value = (const float*)d_in[2];
    const float* Wq    = (const float*)d_in[3];
    const float* bq    = (const float*)d_in[4];
    const float* Wk    = (const float*)d_in[5];
    const float* bk    = (const float*)d_in[6];
    const float* Wv    = (const float*)d_in[7];
    const float* bv    = (const float*)d_in[8];
    float* out = (float*)d_out;

    // Zero the ENTIRE output (out region is now atomically accumulated too).
    cudaMemsetAsync(out, 0,
                    (size_t)(BB * SS * DD + (size_t)BB * SS * SS) * sizeof(float));

    cudaFuncSetAttribute(proj_all,
                         cudaFuncAttributeMaxDynamicSharedMemorySize, PROJ_SMEM);
    dim3 pg(DD / 128, (BB * SS) / 128, 3);
    proj_all<<<pg, 256, PROJ_SMEM>>>(query, key_, value, Wq, Wk, Wv, bq, bk, bv);

    cudaFuncSetAttribute(attn_kernel,
                         cudaFuncAttributeMaxDynamicSharedMemorySize, SMEM_BYTES);
    attn_kernel<<<BB * HH * (SS / 16), 512, SMEM_BYTES>>>(out);
}

// round 12
// speedup vs baseline: 1.8805x; 1.0514x over previous
#include <cuda_runtime.h>
#include <cstdint>

#define BB 2
#define SS 2048
#define DD 1024
#define HH 16
#define HD 64

// Scratch: g_Q [b,h][s][64]; g_K TRANSPOSED [b,h][d][s]; g_V [b,h][s][64].
__device__ float g_Q[BB*HH*SS*HD];
__device__ float g_K[BB*HH*SS*HD];
__device__ float g_V[BB*HH*SS*HD];

// ---------------------------------------------------------------------------
// Packed f32x2 helpers (exact IEEE fp32 per lane).
// ---------------------------------------------------------------------------
typedef unsigned long long u64cu;
union F4U2 { float4 f4; u64cu u2[2]; };

__device__ __forceinline__ u64cu dup2(float x) {
    u64cu r; asm("mov.b64 %0, {%1, %1};" : "=l"(r) : "f"(x)); return r;
}
__device__ __forceinline__ void fma2(u64cu& c, u64cu a, u64cu b) {
    asm("fma.rn.f32x2 %0, %1, %2, %0;" : "+l"(c) : "l"(a), "l"(b));
}
__device__ __forceinline__ float2 up2(u64cu v) {
    float2 f; asm("mov.b64 {%0, %1}, %2;" : "=f"(f.x), "=f"(f.y) : "l"(v));
    return f;
}

// ---------------------------------------------------------------------------
// tf32 mma.sync helpers (downstream-of-softmax paths only).
// ---------------------------------------------------------------------------
__device__ __forceinline__ uint32_t f2tf32(float x) {
    uint32_t r;
    asm("cvt.rna.tf32.f32 %0, %1;" : "=r"(r) : "f"(x));
    return r;
}
__device__ __forceinline__ void split_tf32(float v, float& hi, float& lo) {
    uint32_t hb;
    asm("cvt.rna.tf32.f32 %0, %1;" : "=r"(hb) : "f"(v));
    hi = __uint_as_float(hb);
    float r = v - hi;
    uint32_t lb;
    asm("cvt.rna.tf32.f32 %0, %1;" : "=r"(lb) : "f"(r));
    lo = __uint_as_float(lb);
}
__device__ __forceinline__ void mma8(float* c, const uint32_t* a, const uint32_t* bf) {
    asm volatile("mma.sync.aligned.m16n8k8.row.col.f32.tf32.tf32.f32 "
                 "{%0,%1,%2,%3}, {%4,%5,%6,%7}, {%8,%9}, {%0,%1,%2,%3};"
                 : "+f"(c[0]), "+f"(c[1]), "+f"(c[2]), "+f"(c[3])
                 : "r"(a[0]), "r"(a[1]), "r"(a[2]), "r"(a[3]),
                   "r"(bf[0]), "r"(bf[1]));
}

// ---------------------------------------------------------------------------
// ALL projections in ONE launch, grid (8, 32, 3):
//   z=0 -> Q fp32 SIMT;  z=1 -> K fp32 SIMT (TRANSPOSED);  z=2 -> V 3xTF32.
// ---------------------------------------------------------------------------
#define PJ_STR 36
#define PROJ_SMEM (4 * 128 * PJ_STR * 4)

__global__ void __launch_bounds__(256, 2)
proj_all(const float* __restrict__ Xq, const float* __restrict__ Xk,
         const float* __restrict__ Xv,
         const float* __restrict__ Wq, const float* __restrict__ Wk,
         const float* __restrict__ Wv,
         const float* __restrict__ bq, const float* __restrict__ bk,
         const float* __restrict__ bv)
{
    extern __shared__ float ps[];
    const int z   = blockIdx.z;
    const int bi  = blockIdx.y * 128;
    const int bj  = blockIdx.x * 128;
    const int tid = threadIdx.x;

    if (z < 2) {
        const float* X    = z ? Xk : Xq;
        const float* W    = z ? Wk : Wq;
        const float* bias = z ? bk : bq;
        float* dst        = z ? g_K : g_Q;

        float* As = ps;
        float* Bs = ps + 8 * 128;

        const int tx = tid & 15;
        const int ty = tid >> 4;
        const int lr = tid >> 1;
        const int lc = (tid & 1) * 4;

        const float* Xp = X + (size_t)(bi + lr) * DD + lc;
        const float* Wp = W + (size_t)(bj + lr) * DD + lc;

        u64cu accp[8][4];
#pragma unroll
        for (int i = 0; i < 8; i++)
#pragma unroll
            for (int p = 0; p < 4; p++) accp[i][p] = 0ULL;

        for (int k0 = 0; k0 < DD; k0 += 8) {
            float4 a4 = *(const float4*)(Xp + k0);
            float4 w4 = *(const float4*)(Wp + k0);
            As[(lc + 0) * 128 + lr] = a4.x; As[(lc + 1) * 128 + lr] = a4.y;
            As[(lc + 2) * 128 + lr] = a4.z; As[(lc + 3) * 128 + lr] = a4.w;
            Bs[(lc + 0) * 128 + lr] = w4.x; Bs[(lc + 1) * 128 + lr] = w4.y;
            Bs[(lc + 2) * 128 + lr] = w4.z; Bs[(lc + 3) * 128 + lr] = w4.w;
            __syncthreads();

#pragma unroll
            for (int k = 0; k < 8; k++) {
                float av[8];
                F4U2 B0, B1;
                *(float4*)&av[0] = *(const float4*)&As[k * 128 + ty * 8];
                *(float4*)&av[4] = *(const float4*)&As[k * 128 + ty * 8 + 4];
                B0.f4 = *(const float4*)&Bs[k * 128 + tx * 8];
                B1.f4 = *(const float4*)&Bs[k * 128 + tx * 8 + 4];
                const u64cu bp0 = B0.u2[0], bp1 = B0.u2[1];
                const u64cu bp2 = B1.u2[0], bp3 = B1.u2[1];
#pragma unroll
                for (int i = 0; i < 8; i++) {
                    const u64cu ai = dup2(av[i]);
                    fma2(accp[i][0], ai, bp0);
                    fma2(accp[i][1], ai, bp1);
                    fma2(accp[i][2], ai, bp2);
                    fma2(accp[i][3], ai, bp3);
                }
            }
            __syncthreads();
        }

        const int b  = (bi + ty * 8) >> 11;
        const int s0 = (bi + ty * 8) & 2047;

        if (z == 0) {
#pragma unroll
            for (int ii = 0; ii < 8; ii++) {
                const int s = s0 + ii;
#pragma unroll
                for (int p = 0; p < 4; p++) {
                    const int j = bj + tx * 8 + 2 * p;
                    const int h = j >> 6;
                    const int d = j & 63;
                    float2 v = up2(accp[ii][p]);
                    v.x += bias[j];
                    v.y += bias[j + 1];
                    *(float2*)&dst[(((size_t)(b * HH + h)) * SS + s) * HD + d] = v;
                }
            }
        } else {
#pragma unroll
            for (int p = 0; p < 4; p++) {
                const int j = bj + tx * 8 + 2 * p;
                float v0[8], v1[8];
#pragma unroll
                for (int ii = 0; ii < 8; ii++) {
                    float2 v = up2(accp[ii][p]);
                    v0[ii] = v.x + bias[j];
                    v1[ii] = v.y + bias[j + 1];
                }
                const int h0 = j >> 6, d0 = j & 63;
                const int h1 = (j + 1) >> 6, d1 = (j + 1) & 63;
                float* p0 = &dst[(((size_t)(b * HH + h0)) * HD + d0) * SS + s0];
                float* p1 = &dst[(((size_t)(b * HH + h1)) * HD + d1) * SS + s0];
                *(float4*)p0       = *(float4*)&v0[0];
                *(float4*)(p0 + 4) = *(float4*)&v0[4];
                *(float4*)p1       = *(float4*)&v1[0];
                *(float4*)(p1 + 4) = *(float4*)&v1[4];
            }
        }
        return;
    }

    // ================= V: 3xTF32 mma.sync (terminal path) ===================
    {
        const float* X    = Xv;
        const float* W    = Wv;
        const float* bias = bv;
        float* dst        = g_V;

        float* sXh = ps;
        float* sXl = ps + 128 * PJ_STR;
        float* sWh = ps + 2 * 128 * PJ_STR;
        float* sWl = ps + 3 * 128 * PJ_STR;

        const int wid  = tid >> 5;
        const int lane = tid & 31;
        const int wm = wid >> 2;
        const int wn = wid & 3;
        const int lr = lane >> 2;
        const int lc = lane & 3;

        float c[4][4][4];
#pragma unroll
        for (int i = 0; i < 4; i++)
#pragma unroll
            for (int j = 0; j < 4; j++)
#pragma unroll
                for (int e = 0; e < 4; e++) c[i][j][e] = 0.0f;

        for (int ch = 0; ch < 32; ch++) {
            const int k0 = ch * 32;
#pragma unroll
            for (int it = 0; it < 4; it++) {
                const int idx = tid + it * 256;
                const int row = idx >> 3;
                const int q   = (idx & 7) * 4;
                float4 xv = *(const float4*)&X[(size_t)(bi + row) * DD + k0 + q];
                float4 wv = *(const float4*)&W[(size_t)(bj + row) * DD + k0 + q];
                float xh[4], xl[4], wh[4], wl[4];
                const float* xs = (const float*)&xv;
                const float* ws = (const float*)&wv;
#pragma unroll
                for (int e = 0; e < 4; e++) {
                    split_tf32(xs[e], xh[e], xl[e]);
                    split_tf32(ws[e], wh[e], wl[e]);
                }
                *(float4*)&sXh[row * PJ_STR + q] = *(float4*)xh;
                *(float4*)&sXl[row * PJ_STR + q] = *(float4*)xl;
                *(float4*)&sWh[row * PJ_STR + q] = *(float4*)wh;
                *(float4*)&sWl[row * PJ_STR + q] = *(float4*)wl;
            }
            __syncthreads();

#pragma unroll
            for (int k8 = 0; k8 < 4; k8++) {
                const int kc = k8 * 8;
                uint32_t bh[4][2], bl[4][2];
#pragma unroll
                for (int nt = 0; nt < 4; nt++) {
                    const int nr = (wn * 32 + nt * 8 + lr) * PJ_STR + kc + lc;
                    bh[nt][0] = __float_as_uint(sWh[nr]);
                    bh[nt][1] = __float_as_uint(sWh[nr + 4]);
                    bl[nt][0] = __float_as_uint(sWl[nr]);
                    bl[nt][1] = __float_as_uint(sWl[nr + 4]);
                }
#pragma unroll
                for (int mt = 0; mt < 4; mt++) {
                    const int ar = (wm * 64 + mt * 16 + lr) * PJ_STR + kc + lc;
                    uint32_t ah[4], al[4];
                    ah[0] = __float_as_uint(sXh[ar]);
                    ah[1] = __float_as_uint(sXh[ar + 8 * PJ_STR]);
                    ah[2] = __float_as_uint(sXh[ar + 4]);
                    ah[3] = __float_as_uint(sXh[ar + 8 * PJ_STR + 4]);
                    al[0] = __float_as_uint(sXl[ar]);
                    al[1] = __float_as_uint(sXl[ar + 8 * PJ_STR]);
                    al[2] = __float_as_uint(sXl[ar + 4]);
                    al[3] = __float_as_uint(sXl[ar + 8 * PJ_STR + 4]);
#pragma unroll
                    for (int nt = 0; nt < 4; nt++) {
                        mma8(c[mt][nt], ah, bh[nt]);
                        mma8(c[mt][nt], ah, bl[nt]);
                        mma8(c[mt][nt], al, bh[nt]);
                    }
                }
            }
            __syncthreads();
        }

#pragma unroll
        for (int mt = 0; mt < 4; mt++) {
            const int i0 = bi + wm * 64 + mt * 16 + lr;
#pragma unroll
            for (int nt = 0; nt < 4; nt++) {
                const int j = bj + wn * 32 + nt * 8 + 2 * lc;
                const float b0 = bias[j], b1 = bias[j + 1];
                const int h = j >> 6;
                const int d = j & 63;
                {
                    const int bb = i0 >> 11, s = i0 & 2047;
                    float2 v = make_float2(c[mt][nt][0] + b0, c[mt][nt][1] + b1);
                    *(float2*)&dst[(((size_t)(bb * HH + h)) * SS + s) * HD + d] = v;
                }
                {
                    const int i1 = i0 + 8;
                    const int bb = i1 >> 11, s = i1 & 2047;
                    float2 v = make_float2(c[mt][nt][2] + b0, c[mt][nt][3] + b1);
                    *(float2*)&dst[(((size_t)(bb * HH + h)) * SS + s) * HD + d] = v;
                }
            }
        }
    }
}

// ---------------------------------------------------------------------------
// Fused attention per (b, h, 16-row q-block). 512 threads (16 warps).
//   Phase 1: fp32 QK^T, register-prefetch pipelined K chunks (bit-exact raw).
//   Phase 2: softmax stores e (unnormalized); inv -> smem; attn_mean fused.
//   Phase 3: attn @ V tf32 mma, V stride 72 (conflict-free), V prefetch,
//            A-frags scaled by inv (bit-identical to normalized path),
//            partials red.global.add.v2 into pre-zeroed out.
// SMEM: sc 16x2052 | kv 18432 (K [64][256] / V [256][72]) | qt 1024 | sinv 16.
// ---------------------------------------------------------------------------
#define SC_STR 2052
#define KV_FLOATS 18432
#define SMEM_FLOATS (16 * SC_STR + KV_FLOATS + 1024 + 16)
#define SMEM_BYTES  (SMEM_FLOATS * 4)

__global__ void __launch_bounds__(512) attn_kernel(float* __restrict__ out)
{
    extern __shared__ float sm[];
    float* sc   = sm;                        // scores (e), [16][2052]
    float* kv   = sm + 16 * SC_STR;          // K chunk / V chunk
    float* qt   = sm + 16 * SC_STR + KV_FLOATS;   // Q^T [64][16]
    float* sinv = qt + 1024;                 // [16] row inv factors

    const int cta = blockIdx.x;
    const int qb  = cta & 127;
    const int h   = (cta >> 7) & 15;
    const int b   = cta >> 11;
    const int q0  = qb * 16;
    const int tid = threadIdx.x;
    const int wid  = tid >> 5;
    const int lane = tid & 31;

    const float* Qg = g_Q + ((size_t)(b * HH + h) * SS + q0) * HD;
    const float* Kg = g_K + (size_t)(b * HH + h) * HD * SS;   // [d][s]
    const float* Vg = g_V + (size_t)(b * HH + h) * SS * HD;

    if (tid < 256) {
        const int r  = tid >> 4;
        const int c4 = (tid & 15) * 4;
        float4 v = *(const float4*)&Qg[r * HD + c4];
        qt[(c4 + 0) * 16 + r] = v.x;
        qt[(c4 + 1) * 16 + r] = v.y;
        qt[(c4 + 2) * 16 + r] = v.z;
        qt[(c4 + 3) * 16 + r] = v.w;
    }

    // ---- Phase 1: raw = Q K^T (fp32, round-7 order); sc = 1/(8 raw) ----
    const int rg  = tid >> 7;
    const int cg  = tid & 127;
    const int r0  = rg * 4;
    const int cg2 = cg * 2;

    {
        float4 kr[8];
        // prologue: load chunk 0
#pragma unroll
        for (int i = 0; i < 8; i++) {
            const int f  = tid + i * 512;
            const int d  = f >> 6;
            const int c4 = (f & 63) * 4;
            kr[i] = *(const float4*)(Kg + (size_t)d * SS + c4);
        }
#pragma unroll
        for (int i = 0; i < 8; i++) {
            const int f  = tid + i * 512;
            const int d  = f >> 6;
            const int c4 = (f & 63) * 4;
            *(float4*)&kv[d * 256 + c4] = kr[i];
        }
        __syncthreads();

        for (int kc = 0; kc < 8; kc++) {
            // prefetch next chunk into regs (overlaps with compute below)
            if (kc < 7) {
#pragma unroll
                for (int i = 0; i < 8; i++) {
                    const int f  = tid + i * 512;
                    const int d  = f >> 6;
                    const int c4 = (f & 63) * 4;
                    kr[i] = *(const float4*)(Kg + (size_t)d * SS
                                             + (kc + 1) * 256 + c4);
                }
            }

            u64cu a01c0 = 0ULL, a23c0 = 0ULL, a01c1 = 0ULL, a23c1 = 0ULL;
#pragma unroll 8
            for (int d = 0; d < 64; d++) {
                F4U2 qv;
                qv.f4 = *(const float4*)&qt[d * 16 + r0];
                const u64cu q01 = qv.u2[0], q23 = qv.u2[1];
                float2 kvv = *(const float2*)&kv[d * 256 + cg2];
                const u64cu k0d = dup2(kvv.x);
                const u64cu k1d = dup2(kvv.y);
                fma2(a01c0, q01, k0d);
                fma2(a23c0, q23, k0d);
                fma2(a01c1, q01, k1d);
                fma2(a23c1, q23, k1d);
            }

            {
                float2 c0lo = up2(a01c0), c0hi = up2(a23c0);
                float2 c1lo = up2(a01c1), c1hi = up2(a23c1);
                float rowv[4][2] = {{c0lo.x, c1lo.x}, {c0lo.y, c1lo.y},
                                    {c0hi.x, c1hi.x}, {c0hi.y, c1hi.y}};
#pragma unroll
                for (int i = 0; i < 4; i++) {
                    float2 sv;
                    sv.x = __fdividef(1.0f, 8.0f * rowv[i][0]);
                    sv.y = __fdividef(1.0f, 8.0f * rowv[i][1]);
                    *(float2*)&sc[(r0 + i) * SC_STR + kc * 256 + cg2] = sv;
                }
            }
            __syncthreads();          // everyone done reading kv
            if (kc < 7) {
#pragma unroll
                for (int i = 0; i < 8; i++) {
                    const int f  = tid + i * 512;
                    const int d  = f >> 6;
                    const int c4 = (f & 63) * 4;
                    *(float4*)&kv[d * 256 + c4] = kr[i];
                }
                __syncthreads();      // chunk kc+1 visible
            }
        }
    }

    // ---- Phase 2: softmax (store e only) + fused attn_mean ----
    {
        float* row = sc + wid * SC_STR;
        float m = -3.4e38f;
        for (int k = lane; k < 2048; k += 32) m = fmaxf(m, row[k]);
#pragma unroll
        for (int o = 16; o; o >>= 1) m = fmaxf(m, __shfl_xor_sync(0xffffffffu, m, o));
        float ssum = 0.0f;
        for (int k = lane; k < 2048; k += 32) {
            float e = __expf(row[k] - m);
            row[k] = e;
            ssum += e;
        }
#pragma unroll
        for (int o = 16; o; o >>= 1) ssum += __shfl_xor_sync(0xffffffffu, ssum, o);
        const float inv = __fdividef(1.0f, ssum);
        if (lane == 0) sinv[wid] = inv;

        const float invm = inv * 0.0625f;    // exact: x2^-4
        float* am = out + (size_t)BB * SS * DD
                  + ((size_t)(b * SS + q0 + wid)) * SS;
        for (int k4 = lane * 4; k4 < 2048; k4 += 128) {
            float4 v = *(const float4*)&row[k4];
            float4 vm = make_float4(v.x * invm, v.y * invm,
                                    v.z * invm, v.w * invm);
            asm volatile("red.global.add.v4.f32 [%0], {%1, %2, %3, %4};"
                         :: "l"(am + k4), "f"(vm.x), "f"(vm.y), "f"(vm.z), "f"(vm.w)
                         : "memory");
        }
    }
    __syncthreads();

    // ---- Phase 3: out += (e*inv) @ V via tf32 mma, V prefetch pipeline ----
    {
        const int lr = lane >> 2;
        const int lc = lane & 3;
        const float inv_lo = sinv[lr];
        const float inv_hi = sinv[lr + 8];

        float c[8][4];
#pragma unroll
        for (int nt = 0; nt < 8; nt++)
#pragma unroll
            for (int e = 0; e < 4; e++) c[nt][e] = 0.0f;

        float4 vr[8];
        // prologue: load V chunk 0
        {
            const float4* Vc4 = (const float4*)Vg;
#pragma unroll
            for (int i = 0; i < 8; i++) vr[i] = Vc4[tid + i * 512];
#pragma unroll
            for (int i = 0; i < 8; i++) {
                const int f   = tid + i * 512;
                const int row = f >> 4;
                const int nq  = (f & 15) * 4;
                *(float4*)&kv[row * 72 + nq] = vr[i];
            }
        }
        __syncthreads();

        for (int vc = 0; vc < 8; vc++) {
            if (vc < 7) {
                const float4* Vc4 = (const float4*)(Vg + (size_t)(vc + 1) * 256 * HD);
#pragma unroll
                for (int i = 0; i < 8; i++) vr[i] = Vc4[tid + i * 512];
            }

#pragma unroll
            for (int t = 0; t < 2; t++) {
                const int kc = (wid * 2 + t) * 8;
                uint32_t a[4];
                const int ac = vc * 256 + kc + lc;
                a[0] = f2tf32(sc[lr * SC_STR + ac] * inv_lo);
                a[1] = f2tf32(sc[(lr + 8) * SC_STR + ac] * inv_hi);
                a[2] = f2tf32(sc[lr * SC_STR + ac + 4] * inv_lo);
                a[3] = f2tf32(sc[(lr + 8) * SC_STR + ac + 4] * inv_hi);
#pragma unroll
                for (int nt = 0; nt < 8; nt++) {
                    uint32_t bf[2];
                    const int n = nt * 8 + lr;
                    bf[0] = f2tf32(kv[(kc + lc) * 72 + n]);
                    bf[1] = f2tf32(kv[(kc + lc + 4) * 72 + n]);
                    mma8(c[nt], a, bf);
                }
            }
            __syncthreads();
            if (vc < 7) {
#pragma unroll
                for (int i = 0; i < 8; i++) {
                    const int f   = tid + i * 512;
                    const int row = f >> 4;
                    const int nq  = (f & 15) * 4;
                    *(float4*)&kv[row * 72 + nq] = vr[i];
                }
                __syncthreads();
            }
        }

        float* ob = out + ((size_t)(b * SS + q0)) * DD + h * HD;
#pragma unroll
        for (int nt = 0; nt < 8; nt++) {
            const int col = nt * 8 + 2 * lc;
            float* p0 = ob + (size_t)lr * DD + col;
            float* p1 = ob + (size_t)(lr + 8) * DD + col;
            asm volatile("red.global.add.v2.f32 [%0], {%1, %2};"
                         :: "l"(p0), "f"(c[nt][0]), "f"(c[nt][1]) : "memory");
            asm volatile("red.global.add.v2.f32 [%0], {%1, %2};"
                         :: "l"(p1), "f"(c[nt][2]), "f"(c[nt][3]) : "memory");
        }
    }
}

// ---------------------------------------------------------------------------
extern "C" void kernel_launch(void* const* d_in, const int* in_sizes, int n_in,
                              void* d_out, int out_size)
{
    const float* query = (const float*)d_in[0];
    const float* key_  = (const float*)d_in[1];
    const float* value = (const float*)d_in[2];
    const float* Wq    = (const float*)d_in[3];
    const float* bq    = (const float*)d_in[4];
    const float* Wk    = (const float*)d_in[5];
    const float* bk    = (const float*)d_in[6];
    const float* Wv    = (const float*)d_in[7];
    const float* bv    = (const float*)d_in[8];
    float* out = (float*)d_out;

    cudaMemsetAsync(out, 0,
                    (size_t)(BB * SS * DD + (size_t)BB * SS * SS) * sizeof(float));

    cudaFuncSetAttribute(proj_all,
                         cudaFuncAttributeMaxDynamicSharedMemorySize, PROJ_SMEM);
    dim3 pg(DD / 128, (BB * SS) / 128, 3);
    proj_all<<<pg, 256, PROJ_SMEM>>>(query, key_, value, Wq, Wk, Wv, bq, bk, bv);

    cudaFuncSetAttribute(attn_kernel,
                         cudaFuncAttributeMaxDynamicSharedMemorySize, SMEM_BYTES);
    attn_kernel<<<BB * HH * (SS / 16), 512, SMEM_BYTES>>>(out);
}

// round 13
// speedup vs baseline: 2.0521x; 1.0913x over previous
#include <cuda_runtime.h>
#include <cstdint>

#define BB 2
#define SS 2048
#define DD 1024
#define HH 16
#define HD 64

// Scratch: g_Q [b,h][s][64]; g_K TRANSPOSED [b,h][d][s]; g_V [b,h][s][64]
// (V values pre-rounded to tf32 in proj — terminal path, bit-identical out).
__device__ float g_Q[BB*HH*SS*HD];
__device__ float g_K[BB*HH*SS*HD];
__device__ float g_V[BB*HH*SS*HD];

// ---------------------------------------------------------------------------
// Packed f32x2 helpers (exact IEEE fp32 per lane).
// ---------------------------------------------------------------------------
typedef unsigned long long u64cu;
union F4U2 { float4 f4; u64cu u2[2]; };

__device__ __forceinline__ u64cu dup2(float x) {
    u64cu r; asm("mov.b64 %0, {%1, %1};" : "=l"(r) : "f"(x)); return r;
}
__device__ __forceinline__ void fma2(u64cu& c, u64cu a, u64cu b) {
    asm("fma.rn.f32x2 %0, %1, %2, %0;" : "+l"(c) : "l"(a), "l"(b));
}
__device__ __forceinline__ float2 up2(u64cu v) {
    float2 f; asm("mov.b64 {%0, %1}, %2;" : "=f"(f.x), "=f"(f.y) : "l"(v));
    return f;
}

// ---------------------------------------------------------------------------
// tf32 mma.sync helpers (downstream-of-softmax paths only).
// ---------------------------------------------------------------------------
__device__ __forceinline__ uint32_t f2tf32(float x) {
    uint32_t r;
    asm("cvt.rna.tf32.f32 %0, %1;" : "=r"(r) : "f"(x));
    return r;
}
__device__ __forceinline__ void split_tf32(float v, float& hi, float& lo) {
    uint32_t hb;
    asm("cvt.rna.tf32.f32 %0, %1;" : "=r"(hb) : "f"(v));
    hi = __uint_as_float(hb);
    float r = v - hi;
    uint32_t lb;
    asm("cvt.rna.tf32.f32 %0, %1;" : "=r"(lb) : "f"(r));
    lo = __uint_as_float(lb);
}
__device__ __forceinline__ void mma8(float* c, const uint32_t* a, const uint32_t* bf) {
    asm volatile("mma.sync.aligned.m16n8k8.row.col.f32.tf32.tf32.f32 "
                 "{%0,%1,%2,%3}, {%4,%5,%6,%7}, {%8,%9}, {%0,%1,%2,%3};"
                 : "+f"(c[0]), "+f"(c[1]), "+f"(c[2]), "+f"(c[3])
                 : "r"(a[0]), "r"(a[1]), "r"(a[2]), "r"(a[3]),
                   "r"(bf[0]), "r"(bf[1]));
}

// cp.async (Ampere+ PTX; fine on plain sm_100 target).
__device__ __forceinline__ uint32_t smem_addr(const void* p) {
    return (uint32_t)__cvta_generic_to_shared(p);
}
__device__ __forceinline__ void cpasync16(uint32_t dst, const void* src) {
    asm volatile("cp.async.cg.shared.global [%0], [%1], 16;"
                 :: "r"(dst), "l"(src) : "memory");
}
#define CP_COMMIT() asm volatile("cp.async.commit_group;" ::: "memory")
#define CP_WAIT0()  asm volatile("cp.async.wait_group 0;" ::: "memory")

// ---------------------------------------------------------------------------
// ALL projections in ONE launch, grid (8, 32, 3):
//   z=0 -> Q fp32 SIMT;  z=1 -> K fp32 SIMT (TRANSPOSED);  z=2 -> V 3xTF32.
// ---------------------------------------------------------------------------
#define PJ_STR 36
#define PROJ_SMEM (4 * 128 * PJ_STR * 4)

__global__ void __launch_bounds__(256, 2)
proj_all(const float* __restrict__ Xq, const float* __restrict__ Xk,
         const float* __restrict__ Xv,
         const float* __restrict__ Wq, const float* __restrict__ Wk,
         const float* __restrict__ Wv,
         const float* __restrict__ bq, const float* __restrict__ bk,
         const float* __restrict__ bv)
{
    extern __shared__ float ps[];
    const int z   = blockIdx.z;
    const int bi  = blockIdx.y * 128;
    const int bj  = blockIdx.x * 128;
    const int tid = threadIdx.x;

    if (z < 2) {
        const float* X    = z ? Xk : Xq;
        const float* W    = z ? Wk : Wq;
        const float* bias = z ? bk : bq;
        float* dst        = z ? g_K : g_Q;

        float* As = ps;
        float* Bs = ps + 8 * 128;

        const int tx = tid & 15;
        const int ty = tid >> 4;
        const int lr = tid >> 1;
        const int lc = (tid & 1) * 4;

        const float* Xp = X + (size_t)(bi + lr) * DD + lc;
        const float* Wp = W + (size_t)(bj + lr) * DD + lc;

        u64cu accp[8][4];
#pragma unroll
        for (int i = 0; i < 8; i++)
#pragma unroll
            for (int p = 0; p < 4; p++) accp[i][p] = 0ULL;

        for (int k0 = 0; k0 < DD; k0 += 8) {
            float4 a4 = *(const float4*)(Xp + k0);
            float4 w4 = *(const float4*)(Wp + k0);
            As[(lc + 0) * 128 + lr] = a4.x; As[(lc + 1) * 128 + lr] = a4.y;
            As[(lc + 2) * 128 + lr] = a4.z; As[(lc + 3) * 128 + lr] = a4.w;
            Bs[(lc + 0) * 128 + lr] = w4.x; Bs[(lc + 1) * 128 + lr] = w4.y;
            Bs[(lc + 2) * 128 + lr] = w4.z; Bs[(lc + 3) * 128 + lr] = w4.w;
            __syncthreads();

#pragma unroll
            for (int k = 0; k < 8; k++) {
                float av[8];
                F4U2 B0, B1;
                *(float4*)&av[0] = *(const float4*)&As[k * 128 + ty * 8];
                *(float4*)&av[4] = *(const float4*)&As[k * 128 + ty * 8 + 4];
                B0.f4 = *(const float4*)&Bs[k * 128 + tx * 8];
                B1.f4 = *(const float4*)&Bs[k * 128 + tx * 8 + 4];
                const u64cu bp0 = B0.u2[0], bp1 = B0.u2[1];
                const u64cu bp2 = B1.u2[0], bp3 = B1.u2[1];
#pragma unroll
                for (int i = 0; i < 8; i++) {
                    const u64cu ai = dup2(av[i]);
                    fma2(accp[i][0], ai, bp0);
                    fma2(accp[i][1], ai, bp1);
                    fma2(accp[i][2], ai, bp2);
                    fma2(accp[i][3], ai, bp3);
                }
            }
            __syncthreads();
        }

        const int b  = (bi + ty * 8) >> 11;
        const int s0 = (bi + ty * 8) & 2047;

        if (z == 0) {
#pragma unroll
            for (int ii = 0; ii < 8; ii++) {
                const int s = s0 + ii;
#pragma unroll
                for (int p = 0; p < 4; p++) {
                    const int j = bj + tx * 8 + 2 * p;
                    const int h = j >> 6;
                    const int d = j & 63;
                    float2 v = up2(accp[ii][p]);
                    v.x += bias[j];
                    v.y += bias[j + 1];
                    *(float2*)&dst[(((size_t)(b * HH + h)) * SS + s) * HD + d] = v;
                }
            }
        } else {
#pragma unroll
            for (int p = 0; p < 4; p++) {
                const int j = bj + tx * 8 + 2 * p;
                float v0[8], v1[8];
#pragma unroll
                for (int ii = 0; ii < 8; ii++) {
                    float2 v = up2(accp[ii][p]);
                    v0[ii] = v.x + bias[j];
                    v1[ii] = v.y + bias[j + 1];
                }
                const int h0 = j >> 6, d0 = j & 63;
                const int h1 = (j + 1) >> 6, d1 = (j + 1) & 63;
                float* p0 = &dst[(((size_t)(b * HH + h0)) * HD + d0) * SS + s0];
                float* p1 = &dst[(((size_t)(b * HH + h1)) * HD + d1) * SS + s0];
                *(float4*)p0       = *(float4*)&v0[0];
                *(float4*)(p0 + 4) = *(float4*)&v0[4];
                *(float4*)p1       = *(float4*)&v1[0];
                *(float4*)(p1 + 4) = *(float4*)&v1[4];
            }
        }
        return;
    }

    // ================= V: 3xTF32 mma.sync (terminal path) ===================
    {
        const float* X    = Xv;
        const float* W    = Wv;
        const float* bias = bv;
        float* dst        = g_V;

        float* sXh = ps;
        float* sXl = ps + 128 * PJ_STR;
        float* sWh = ps + 2 * 128 * PJ_STR;
        float* sWl = ps + 3 * 128 * PJ_STR;

        const int wid  = tid >> 5;
        const int lane = tid & 31;
        const int wm = wid >> 2;
        const int wn = wid & 3;
        const int lr = lane >> 2;
        const int lc = lane & 3;

        float c[4][4][4];
#pragma unroll
        for (int i = 0; i < 4; i++)
#pragma unroll
            for (int j = 0; j < 4; j++)
#pragma unroll
                for (int e = 0; e < 4; e++) c[i][j][e] = 0.0f;

        for (int ch = 0; ch < 32; ch++) {
            const int k0 = ch * 32;
#pragma unroll
            for (int it = 0; it < 4; it++) {
                const int idx = tid + it * 256;
                const int row = idx >> 3;
                const int q   = (idx & 7) * 4;
                float4 xv = *(const float4*)&X[(size_t)(bi + row) * DD + k0 + q];
                float4 wv = *(const float4*)&W[(size_t)(bj + row) * DD + k0 + q];
                float xh[4], xl[4], wh[4], wl[4];
                const float* xs = (const float*)&xv;
                const float* ws = (const float*)&wv;
#pragma unroll
                for (int e = 0; e < 4; e++) {
                    split_tf32(xs[e], xh[e], xl[e]);
                    split_tf32(ws[e], wh[e], wl[e]);
                }
                *(float4*)&sXh[row * PJ_STR + q] = *(float4*)xh;
                *(float4*)&sXl[row * PJ_STR + q] = *(float4*)xl;
                *(float4*)&sWh[row * PJ_STR + q] = *(float4*)wh;
                *(float4*)&sWl[row * PJ_STR + q] = *(float4*)wl;
            }
            __syncthreads();

#pragma unroll
            for (int k8 = 0; k8 < 4; k8++) {
                const int kc = k8 * 8;
                uint32_t bh[4][2], bl[4][2];
#pragma unroll
                for (int nt = 0; nt < 4; nt++) {
                    const int nr = (wn * 32 + nt * 8 + lr) * PJ_STR + kc + lc;
                    bh[nt][0] = __float_as_uint(sWh[nr]);
                    bh[nt][1] = __float_as_uint(sWh[nr + 4]);
                    bl[nt][0] = __float_as_uint(sWl[nr]);
                    bl[nt][1] = __float_as_uint(sWl[nr + 4]);
                }
#pragma unroll
                for (int mt = 0; mt < 4; mt++) {
                    const int ar = (wm * 64 + mt * 16 + lr) * PJ_STR + kc + lc;
                    uint32_t ah[4], al[4];
                    ah[0] = __float_as_uint(sXh[ar]);
                    ah[1] = __float_as_uint(sXh[ar + 8 * PJ_STR]);
                    ah[2] = __float_as_uint(sXh[ar + 4]);
                    ah[3] = __float_as_uint(sXh[ar + 8 * PJ_STR + 4]);
                    al[0] = __float_as_uint(sXl[ar]);
                    al[1] = __float_as_uint(sXl[ar + 8 * PJ_STR]);
                    al[2] = __float_as_uint(sXl[ar + 4]);
                    al[3] = __float_as_uint(sXl[ar + 8 * PJ_STR + 4]);
#pragma unroll
                    for (int nt = 0; nt < 4; nt++) {
                        mma8(c[mt][nt], ah, bh[nt]);
                        mma8(c[mt][nt], ah, bl[nt]);
                        mma8(c[mt][nt], al, bh[nt]);
                    }
                }
            }
            __syncthreads();
        }

        // Epilogue: bias add, PRE-ROUND to tf32 (bit-identical to cvt at use).
#pragma unroll
        for (int mt = 0; mt < 4; mt++) {
            const int i0 = bi + wm * 64 + mt * 16 + lr;
#pragma unroll
            for (int nt = 0; nt < 4; nt++) {
                const int j = bj + wn * 32 + nt * 8 + 2 * lc;
                const float b0 = bias[j], b1 = bias[j + 1];
                const int h = j >> 6;
                const int d = j & 63;
                {
                    const int bb = i0 >> 11, s = i0 & 2047;
                    float2 v;
                    v.x = __uint_as_float(f2tf32(c[mt][nt][0] + b0));
                    v.y = __uint_as_float(f2tf32(c[mt][nt][1] + b1));
                    *(float2*)&dst[(((size_t)(bb * HH + h)) * SS + s) * HD + d] = v;
                }
                {
                    const int i1 = i0 + 8;
                    const int bb = i1 >> 11, s = i1 & 2047;
                    float2 v;
                    v.x = __uint_as_float(f2tf32(c[mt][nt][2] + b0));
                    v.y = __uint_as_float(f2tf32(c[mt][nt][3] + b1));
                    *(float2*)&dst[(((size_t)(bb * HH + h)) * SS + s) * HD + d] = v;
                }
            }
        }
    }
}

// ---------------------------------------------------------------------------
// Fused attention per (b, h, 16-row q-block). 512 threads (16 warps).
//   Phase 1: fp32 QK^T, cp.async double-buffered [32][256] d-half sub-chunks
//            (accumulation order d=0..63 unchanged -> bit-exact raw).
//   Phase 2: softmax stores e; inv -> smem; attn_mean fused (red.v4).
//   Phase 3: attn @ V tf32 mma, cp.async double-buffered [128][72] sub-chunks
//            (kc = wid*8 per sub); V pre-tf32 -> no cvt on B frags;
//            partials red.global.add.v2 into pre-zeroed out.
// SMEM: sc 16x2052 | buf 2x9216 | qt 1024 | sinv 16  = 209 KB.
// ---------------------------------------------------------------------------
#define SC_STR 2052
#define BUF_FLOATS 9216
#define SMEM_FLOATS (16 * SC_STR + 2 * BUF_FLOATS + 1024 + 16)
#define SMEM_BYTES  (SMEM_FLOATS * 4)

__global__ void __launch_bounds__(512) attn_kernel(float* __restrict__ out)
{
    extern __shared__ float sm[];
    float* sc   = sm;                          // scores (e), [16][2052]
    float* buf0 = sm + 16 * SC_STR;            // pipeline buffer 0
    float* buf1 = buf0 + BUF_FLOATS;           // pipeline buffer 1
    float* qt   = buf0 + 2 * BUF_FLOATS;       // Q^T [64][16]
    float* sinv = qt + 1024;                   // [16] row inv factors

    const int cta = blockIdx.x;
    const int qb  = cta & 127;
    const int h   = (cta >> 7) & 15;
    const int b   = cta >> 11;
    const int q0  = qb * 16;
    const int tid = threadIdx.x;
    const int wid  = tid >> 5;
    const int lane = tid & 31;

    const float* Qg = g_Q + ((size_t)(b * HH + h) * SS + q0) * HD;
    const float* Kg = g_K + (size_t)(b * HH + h) * HD * SS;   // [d][s]
    const float* Vg = g_V + (size_t)(b * HH + h) * SS * HD;

    if (tid < 256) {
        const int r  = tid >> 4;
        const int c4 = (tid & 15) * 4;
        float4 v = *(const float4*)&Qg[r * HD + c4];
        qt[(c4 + 0) * 16 + r] = v.x;
        qt[(c4 + 1) * 16 + r] = v.y;
        qt[(c4 + 2) * 16 + r] = v.z;
        qt[(c4 + 3) * 16 + r] = v.w;
    }

    // ---- Phase 1: raw = Q K^T (fp32, order-preserving); sc = 1/(8 raw) ----
    const int rg  = tid >> 7;
    const int cg  = tid & 127;
    const int r0  = rg * 4;
    const int cg2 = cg * 2;

    {
        // step s: kc = s>>1 (256-col window), dh = s&1 (d-half), buf[s&1].
        const int lf_d = tid >> 6;          // sub-chunk row 0..7 base (i*8)
        const int lf_c = (tid & 63) * 4;    // col offset
        // issue step 0
        {
            float* db = buf0;
#pragma unroll
            for (int i = 0; i < 4; i++) {
                const int dl = lf_d + i * 8;
                cpasync16(smem_addr(&db[dl * 256 + lf_c]),
                          Kg + (size_t)dl * SS + lf_c);
            }
            CP_COMMIT();
        }

        for (int kc = 0; kc < 8; kc++) {
            u64cu a01c0 = 0ULL, a23c0 = 0ULL, a01c1 = 0ULL, a23c1 = 0ULL;
#pragma unroll
            for (int dh = 0; dh < 2; dh++) {
                const int s = kc * 2 + dh;
                CP_WAIT0();
                __syncthreads();
                if (s < 15) {
                    const int s1  = s + 1;
                    const int kc1 = s1 >> 1, dh1 = s1 & 1;
                    float* db = (s1 & 1) ? buf1 : buf0;
#pragma unroll
                    for (int i = 0; i < 4; i++) {
                        const int dl = lf_d + i * 8;
                        cpasync16(smem_addr(&db[dl * 256 + lf_c]),
                                  Kg + (size_t)(dh1 * 32 + dl) * SS
                                     + kc1 * 256 + lf_c);
                    }
                    CP_COMMIT();
                }
                const float* kb = (s & 1) ? buf1 : buf0;
#pragma unroll 8
                for (int dd = 0; dd < 32; dd++) {
                    const int d = dh * 32 + dd;
                    F4U2 qv;
                    qv.f4 = *(const float4*)&qt[d * 16 + r0];
                    const u64cu q01 = qv.u2[0], q23 = qv.u2[1];
                    float2 kvv = *(const float2*)&kb[dd * 256 + cg2];
                    const u64cu k0d = dup2(kvv.x);
                    const u64cu k1d = dup2(kvv.y);
                    fma2(a01c0, q01, k0d);
                    fma2(a23c0, q23, k0d);
                    fma2(a01c1, q01, k1d);
                    fma2(a23c1, q23, k1d);
                }
            }
            {
                float2 c0lo = up2(a01c0), c0hi = up2(a23c0);
                float2 c1lo = up2(a01c1), c1hi = up2(a23c1);
                float rowv[4][2] = {{c0lo.x, c1lo.x}, {c0lo.y, c1lo.y},
                                    {c0hi.x, c1hi.x}, {c0hi.y, c1hi.y}};
#pragma unroll
                for (int i = 0; i < 4; i++) {
                    float2 sv;
                    sv.x = __fdividef(1.0f, 8.0f * rowv[i][0]);
                    sv.y = __fdividef(1.0f, 8.0f * rowv[i][1]);
                    *(float2*)&sc[(r0 + i) * SC_STR + kc * 256 + cg2] = sv;
                }
            }
        }
    }
    __syncthreads();

    // ---- Phase 2: softmax (store e only) + fused attn_mean ----
    {
        float* row = sc + wid * SC_STR;
        float m = -3.4e38f;
        for (int k = lane; k < 2048; k += 32) m = fmaxf(m, row[k]);
#pragma unroll
        for (int o = 16; o; o >>= 1) m = fmaxf(m, __shfl_xor_sync(0xffffffffu, m, o));
        float ssum = 0.0f;
        for (int k = lane; k < 2048; k += 32) {
            float e = __expf(row[k] - m);
            row[k] = e;
            ssum += e;
        }
#pragma unroll
        for (int o = 16; o; o >>= 1) ssum += __shfl_xor_sync(0xffffffffu, ssum, o);
        const float inv = __fdividef(1.0f, ssum);
        if (lane == 0) sinv[wid] = inv;

        const float invm = inv * 0.0625f;
        float* am = out + (size_t)BB * SS * DD
                  + ((size_t)(b * SS + q0 + wid)) * SS;
        for (int k4 = lane * 4; k4 < 2048; k4 += 128) {
            float4 v = *(const float4*)&row[k4];
            float4 vm = make_float4(v.x * invm, v.y * invm,
                                    v.z * invm, v.w * invm);
            asm volatile("red.global.add.v4.f32 [%0], {%1, %2, %3, %4};"
                         :: "l"(am + k4), "f"(vm.x), "f"(vm.y), "f"(vm.z), "f"(vm.w)
                         : "memory");
        }
    }
    __syncthreads();

    // ---- Phase 3: out += (e*inv) @ V via tf32 mma, cp.async pipeline ----
    {
        const int lr = lane >> 2;
        const int lc = lane & 3;
        const float inv_lo = sinv[lr];
        const float inv_hi = sinv[lr + 8];
        const int lf_r = tid >> 4;          // V sub rows 0..31 base (i*32)
        const int lf_n = (tid & 15) * 4;

        float c[8][4];
#pragma unroll
        for (int nt = 0; nt < 8; nt++)
#pragma unroll
            for (int e = 0; e < 4; e++) c[nt][e] = 0.0f;

        // issue step 0 (V rows 0..127)
        {
#pragma unroll
            for (int i = 0; i < 4; i++) {
                const int rl = lf_r + i * 32;
                cpasync16(smem_addr(&buf0[rl * 72 + lf_n]),
                          Vg + (size_t)rl * HD + lf_n);
            }
            CP_COMMIT();
        }

        for (int s = 0; s < 16; s++) {
            CP_WAIT0();
            __syncthreads();
            if (s < 15) {
                float* db = ((s + 1) & 1) ? buf1 : buf0;
#pragma unroll
                for (int i = 0; i < 4; i++) {
                    const int rl = lf_r + i * 32;
                    cpasync16(smem_addr(&db[rl * 72 + lf_n]),
                              Vg + (size_t)((s + 1) * 128 + rl) * HD + lf_n);
                }
                CP_COMMIT();
            }
            const float* vb = (s & 1) ? buf1 : buf0;

            // warp covers k rows [wid*8, wid*8+8) of this 128-row sub-chunk
            uint32_t a[4];
            const int ac = s * 128 + wid * 8 + lc;
            a[0] = f2tf32(sc[lr * SC_STR + ac] * inv_lo);
            a[1] = f2tf32(sc[(lr + 8) * SC_STR + ac] * inv_hi);
            a[2] = f2tf32(sc[lr * SC_STR + ac + 4] * inv_lo);
            a[3] = f2tf32(sc[(lr + 8) * SC_STR + ac + 4] * inv_hi);
            const int kl = wid * 8 + lc;
#pragma unroll
            for (int nt = 0; nt < 8; nt++) {
                uint32_t bf[2];
                const int n = nt * 8 + lr;
                bf[0] = __float_as_uint(vb[kl * 72 + n]);        // pre-tf32
                bf[1] = __float_as_uint(vb[(kl + 4) * 72 + n]);
                mma8(c[nt], a, bf);
            }
        }

        float* ob = out + ((size_t)(b * SS + q0)) * DD + h * HD;
#pragma unroll
        for (int nt = 0; nt < 8; nt++) {
            const int col = nt * 8 + 2 * lc;
            float* p0 = ob + (size_t)lr * DD + col;
            float* p1 = ob + (size_t)(lr + 8) * DD + col;
            asm volatile("red.global.add.v2.f32 [%0], {%1, %2};"
                         :: "l"(p0), "f"(c[nt][0]), "f"(c[nt][1]) : "memory");
            asm volatile("red.global.add.v2.f32 [%0], {%1, %2};"
                         :: "l"(p1), "f"(c[nt][2]), "f"(c[nt][3]) : "memory");
        }
    }
}

// ---------------------------------------------------------------------------
extern "C" void kernel_launch(void* const* d_in, const int* in_sizes, int n_in,
                              void* d_out, int out_size)
{
    const float* query = (const float*)d_in[0];
    const float* key_  = (const float*)d_in[1];
    const float* value = (const float*)d_in[2];
    const float* Wq    = (const float*)d_in[3];
    const float* bq    = (const float*)d_in[4];
    const float* Wk    = (const float*)d_in[5];
    const float* bk    = (const float*)d_in[6];
    const float* Wv    = (const float*)d_in[7];
    const float* bv    = (const float*)d_in[8];
    float* out = (float*)d_out;

    cudaMemsetAsync(out, 0,
                    (size_t)(BB * SS * DD + (size_t)BB * SS * SS) * sizeof(float));

    cudaFuncSetAttribute(proj_all,
                         cudaFuncAttributeMaxDynamicSharedMemorySize, PROJ_SMEM);
    dim3 pg(DD / 128, (BB * SS) / 128, 3);
    proj_all<<<pg, 256, PROJ_SMEM>>>(query, key_, value, Wq, Wk, Wv, bq, bk, bv);

    cudaFuncSetAttribute(attn_kernel,
                         cudaFuncAttributeMaxDynamicSharedMemorySize, SMEM_BYTES);
    attn_kernel<<<BB * HH * (SS / 16), 512, SMEM_BYTES>>>(out);
}

// round 15
// speedup vs baseline: 2.1341x; 1.0400x over previous
#include <cuda_runtime.h>
#include <cstdint>

#define BB 2
#define SS 2048
#define DD 1024
#define HH 16
#define HD 64

// Scratch: g_Q [b,h][s][64]; g_K TRANSPOSED [b,h][d][s]; g_V [b,h][s][64]
// (V values pre-rounded to tf32 in proj — terminal path, bit-identical out).
__device__ float g_Q[BB*HH*SS*HD];
__device__ float g_K[BB*HH*SS*HD];
__device__ float g_V[BB*HH*SS*HD];

// ---------------------------------------------------------------------------
// Packed f32x2 helpers (exact IEEE fp32 per lane).
// ---------------------------------------------------------------------------
typedef unsigned long long u64cu;
union F4U2 { float4 f4; u64cu u2[2]; };

__device__ __forceinline__ u64cu dup2(float x) {
    u64cu r; asm("mov.b64 %0, {%1, %1};" : "=l"(r) : "f"(x)); return r;
}
__device__ __forceinline__ void fma2(u64cu& c, u64cu a, u64cu b) {
    asm("fma.rn.f32x2 %0, %1, %2, %0;" : "+l"(c) : "l"(a), "l"(b));
}
__device__ __forceinline__ float2 up2(u64cu v) {
    float2 f; asm("mov.b64 {%0, %1}, %2;" : "=f"(f.x), "=f"(f.y) : "l"(v));
    return f;
}

// ---------------------------------------------------------------------------
// tf32 mma.sync helpers (downstream-of-softmax paths only).
// ---------------------------------------------------------------------------
__device__ __forceinline__ uint32_t f2tf32(float x) {
    uint32_t r;
    asm("cvt.rna.tf32.f32 %0, %1;" : "=r"(r) : "f"(x));
    return r;
}
__device__ __forceinline__ void split_tf32(float v, float& hi, float& lo) {
    uint32_t hb;
    asm("cvt.rna.tf32.f32 %0, %1;" : "=r"(hb) : "f"(v));
    hi = __uint_as_float(hb);
    float r = v - hi;
    uint32_t lb;
    asm("cvt.rna.tf32.f32 %0, %1;" : "=r"(lb) : "f"(r));
    lo = __uint_as_float(lb);
}
__device__ __forceinline__ void mma8(float* c, const uint32_t* a, const uint32_t* bf) {
    asm volatile("mma.sync.aligned.m16n8k8.row.col.f32.tf32.tf32.f32 "
                 "{%0,%1,%2,%3}, {%4,%5,%6,%7}, {%8,%9}, {%0,%1,%2,%3};"
                 : "+f"(c[0]), "+f"(c[1]), "+f"(c[2]), "+f"(c[3])
                 : "r"(a[0]), "r"(a[1]), "r"(a[2]), "r"(a[3]),
                   "r"(bf[0]), "r"(bf[1]));
}

// cp.async (Ampere+ PTX; fine on plain sm_100 target).
__device__ __forceinline__ uint32_t smem_addr(const void* p) {
    return (uint32_t)__cvta_generic_to_shared(p);
}
__device__ __forceinline__ void cpasync16(uint32_t dst, const void* src) {
    asm volatile("cp.async.cg.shared.global [%0], [%1], 16;"
                 :: "r"(dst), "l"(src) : "memory");
}
#define CP_COMMIT() asm volatile("cp.async.commit_group;" ::: "memory")
#define CP_WAIT0()  asm volatile("cp.async.wait_group 0;" ::: "memory")
#define CP_WAIT1()  asm volatile("cp.async.wait_group 1;" ::: "memory")

// ---------------------------------------------------------------------------
// ALL projections in ONE launch, grid (8, 32, 3):
//   z=0 -> Q fp32 SIMT;  z=1 -> K fp32 SIMT (TRANSPOSED);  z=2 -> V 3xTF32.
// ---------------------------------------------------------------------------
#define PJ_STR 36
#define PROJ_SMEM (4 * 128 * PJ_STR * 4)

__global__ void __launch_bounds__(256, 2)
proj_all(const float* __restrict__ Xq, const float* __restrict__ Xk,
         const float* __restrict__ Xv,
         const float* __restrict__ Wq, const float* __restrict__ Wk,
         const float* __restrict__ Wv,
         const float* __restrict__ bq, const float* __restrict__ bk,
         const float* __restrict__ bv)
{
    extern __shared__ float ps[];
    const int z   = blockIdx.z;
    const int bi  = blockIdx.y * 128;
    const int bj  = blockIdx.x * 128;
    const int tid = threadIdx.x;

    if (z < 2) {
        const float* X    = z ? Xk : Xq;
        const float* W    = z ? Wk : Wq;
        const float* bias = z ? bk : bq;
        float* dst        = z ? g_K : g_Q;

        float* As = ps;
        float* Bs = ps + 8 * 128;

        const int tx = tid & 15;
        const int ty = tid >> 4;
        const int lr = tid >> 1;
        const int lc = (tid & 1) * 4;

        const float* Xp = X + (size_t)(bi + lr) * DD + lc;
        const float* Wp = W + (size_t)(bj + lr) * DD + lc;

        u64cu accp[8][4];
#pragma unroll
        for (int i = 0; i < 8; i++)
#pragma unroll
            for (int p = 0; p < 4; p++) accp[i][p] = 0ULL;

        for (int k0 = 0; k0 < DD; k0 += 8) {
            float4 a4 = *(const float4*)(Xp + k0);
            float4 w4 = *(const float4*)(Wp + k0);
            As[(lc + 0) * 128 + lr] = a4.x; As[(lc + 1) * 128 + lr] = a4.y;
            As[(lc + 2) * 128 + lr] = a4.z; As[(lc + 3) * 128 + lr] = a4.w;
            Bs[(lc + 0) * 128 + lr] = w4.x; Bs[(lc + 1) * 128 + lr] = w4.y;
            Bs[(lc + 2) * 128 + lr] = w4.z; Bs[(lc + 3) * 128 + lr] = w4.w;
            __syncthreads();

#pragma unroll
            for (int k = 0; k < 8; k++) {
                float av[8];
                F4U2 B0, B1;
                *(float4*)&av[0] = *(const float4*)&As[k * 128 + ty * 8];
                *(float4*)&av[4] = *(const float4*)&As[k * 128 + ty * 8 + 4];
                B0.f4 = *(const float4*)&Bs[k * 128 + tx * 8];
                B1.f4 = *(const float4*)&Bs[k * 128 + tx * 8 + 4];
                const u64cu bp0 = B0.u2[0], bp1 = B0.u2[1];
                const u64cu bp2 = B1.u2[0], bp3 = B1.u2[1];
#pragma unroll
                for (int i = 0; i < 8; i++) {
                    const u64cu ai = dup2(av[i]);
                    fma2(accp[i][0], ai, bp0);
                    fma2(accp[i][1], ai, bp1);
                    fma2(accp[i][2], ai, bp2);
                    fma2(accp[i][3], ai, bp3);
                }
            }
            __syncthreads();
        }

        const int b  = (bi + ty * 8) >> 11;
        const int s0 = (bi + ty * 8) & 2047;

        if (z == 0) {
#pragma unroll
            for (int ii = 0; ii < 8; ii++) {
                const int s = s0 + ii;
#pragma unroll
                for (int p = 0; p < 4; p++) {
                    const int j = bj + tx * 8 + 2 * p;
                    const int h = j >> 6;
                    const int d = j & 63;
                    float2 v = up2(accp[ii][p]);
                    v.x += bias[j];
                    v.y += bias[j + 1];
                    *(float2*)&dst[(((size_t)(b * HH + h)) * SS + s) * HD + d] = v;
                }
            }
        } else {
#pragma unroll
            for (int p = 0; p < 4; p++) {
                const int j = bj + tx * 8 + 2 * p;
                float v0[8], v1[8];
#pragma unroll
                for (int ii = 0; ii < 8; ii++) {
                    float2 v = up2(accp[ii][p]);
                    v0[ii] = v.x + bias[j];
                    v1[ii] = v.y + bias[j + 1];
                }
                const int h0 = j >> 6, d0 = j & 63;
                const int h1 = (j + 1) >> 6, d1 = (j + 1) & 63;
                float* p0 = &dst[(((size_t)(b * HH + h0)) * HD + d0) * SS + s0];
                float* p1 = &dst[(((size_t)(b * HH + h1)) * HD + d1) * SS + s0];
                *(float4*)p0       = *(float4*)&v0[0];
                *(float4*)(p0 + 4) = *(float4*)&v0[4];
                *(float4*)p1       = *(float4*)&v1[0];
                *(float4*)(p1 + 4) = *(float4*)&v1[4];
            }
        }
        return;
    }

    // ================= V: 3xTF32 mma.sync (terminal path) ===================
    {
        const float* X    = Xv;
        const float* W    = Wv;
        const float* bias = bv;
        float* dst        = g_V;

        float* sXh = ps;
        float* sXl = ps + 128 * PJ_STR;
        float* sWh = ps + 2 * 128 * PJ_STR;
        float* sWl = ps + 3 * 128 * PJ_STR;

        const int wid  = tid >> 5;
        const int lane = tid & 31;
        const int wm = wid >> 2;
        const int wn = wid & 3;
        const int lr = lane >> 2;
        const int lc = lane & 3;

        float c[4][4][4];
#pragma unroll
        for (int i = 0; i < 4; i++)
#pragma unroll
            for (int j = 0; j < 4; j++)
#pragma unroll
                for (int e = 0; e < 4; e++) c[i][j][e] = 0.0f;

        for (int ch = 0; ch < 32; ch++) {
            const int k0 = ch * 32;
#pragma unroll
            for (int it = 0; it < 4; it++) {
                const int idx = tid + it * 256;
                const int row = idx >> 3;
                const int q   = (idx & 7) * 4;
                float4 xv = *(const float4*)&X[(size_t)(bi + row) * DD + k0 + q];
                float4 wv = *(const float4*)&W[(size_t)(bj + row) * DD + k0 + q];
                float xh[4], xl[4], wh[4], wl[4];
                const float* xs = (const float*)&xv;
                const float* ws = (const float*)&wv;
#pragma unroll
                for (int e = 0; e < 4; e++) {
                    split_tf32(xs[e], xh[e], xl[e]);
                    split_tf32(ws[e], wh[e], wl[e]);
                }
                *(float4*)&sXh[row * PJ_STR + q] = *(float4*)xh;
                *(float4*)&sXl[row * PJ_STR + q] = *(float4*)xl;
                *(float4*)&sWh[row * PJ_STR + q] = *(float4*)wh;
                *(float4*)&sWl[row * PJ_STR + q] = *(float4*)wl;
            }
            __syncthreads();

#pragma unroll
            for (int k8 = 0; k8 < 4; k8++) {
                const int kc = k8 * 8;
                uint32_t bh[4][2], bl[4][2];
#pragma unroll
                for (int nt = 0; nt < 4; nt++) {
                    const int nr = (wn * 32 + nt * 8 + lr) * PJ_STR + kc + lc;
                    bh[nt][0] = __float_as_uint(sWh[nr]);
                    bh[nt][1] = __float_as_uint(sWh[nr + 4]);
                    bl[nt][0] = __float_as_uint(sWl[nr]);
                    bl[nt][1] = __float_as_uint(sWl[nr + 4]);
                }
#pragma unroll
                for (int mt = 0; mt < 4; mt++) {
                    const int ar = (wm * 64 + mt * 16 + lr) * PJ_STR + kc + lc;
                    uint32_t ah[4], al[4];
                    ah[0] = __float_as_uint(sXh[ar]);
                    ah[1] = __float_as_uint(sXh[ar + 8 * PJ_STR]);
                    ah[2] = __float_as_uint(sXh[ar + 4]);
                    ah[3] = __float_as_uint(sXh[ar + 8 * PJ_STR + 4]);
                    al[0] = __float_as_uint(sXl[ar]);
                    al[1] = __float_as_uint(sXl[ar + 8 * PJ_STR]);
                    al[2] = __float_as_uint(sXl[ar + 4]);
                    al[3] = __float_as_uint(sXl[ar + 8 * PJ_STR + 4]);
#pragma unroll
                    for (int nt = 0; nt < 4; nt++) {
                        mma8(c[mt][nt], ah, bh[nt]);
                        mma8(c[mt][nt], ah, bl[nt]);
                        mma8(c[mt][nt], al, bh[nt]);
                    }
                }
            }
            __syncthreads();
        }

        // Epilogue: bias add, PRE-ROUND to tf32 (bit-identical to cvt at use).
#pragma unroll
        for (int mt = 0; mt < 4; mt++) {
            const int i0 = bi + wm * 64 + mt * 16 + lr;
#pragma unroll
            for (int nt = 0; nt < 4; nt++) {
                const int j = bj + wn * 32 + nt * 8 + 2 * lc;
                const float b0 = bias[j], b1 = bias[j + 1];
                const int h = j >> 6;
                const int d = j & 63;
                {
                    const int bb = i0 >> 11, s = i0 & 2047;
                    float2 v;
                    v.x = __uint_as_float(f2tf32(c[mt][nt][0] + b0));
                    v.y = __uint_as_float(f2tf32(c[mt][nt][1] + b1));
                    *(float2*)&dst[(((size_t)(bb * HH + h)) * SS + s) * HD + d] = v;
                }
                {
                    const int i1 = i0 + 8;
                    const int bb = i1 >> 11, s = i1 & 2047;
                    float2 v;
                    v.x = __uint_as_float(f2tf32(c[mt][nt][2] + b0));
                    v.y = __uint_as_float(f2tf32(c[mt][nt][3] + b1));
                    *(float2*)&dst[(((size_t)(bb * HH + h)) * SS + s) * HD + d] = v;
                }
            }
        }
    }
}

// ---------------------------------------------------------------------------
// Fused attention per (b, h, 16-row q-block). 512 threads (16 warps).
//   Phase 1: fp32 QK^T, cp.async double-buffered [32][256] d-half sub-chunks
//            (bit-exact raw; CTA barriers required — true data sharing).
//   Phase 2: softmax stores e; inv -> smem; attn_mean fused (red.v4).
//   Phase 3: WARP-PRIVATE: each warp streams its own 8x72 V slices with
//            per-warp cp.async double-buffering; NO CTA barriers, only
//            __syncwarp. Fragment values/order identical to prior round.
// SMEM: sc 16x2052 | vbuf 18432 (phase1: 2x[32][256]; phase3: 16x2x[8][72])
//       | qt 1024 | sinv 16  = 209 KB.
// ---------------------------------------------------------------------------
#define SC_STR 2052
#define VBUF_FLOATS 18432
#define SMEM_FLOATS (16 * SC_STR + VBUF_FLOATS + 1024 + 16)
#define SMEM_BYTES  (SMEM_FLOATS * 4)

__global__ void __launch_bounds__(512) attn_kernel(float* __restrict__ out)
{
    extern __shared__ float sm[];
    float* sc   = sm;                          // scores (e), [16][2052]
    float* vbuf = sm + 16 * SC_STR;            // shared staging region
    float* qt   = vbuf + VBUF_FLOATS;          // Q^T [64][16]
    float* sinv = qt + 1024;                   // [16] row inv factors

    const int cta = blockIdx.x;
    const int qb  = cta & 127;
    const int h   = (cta >> 7) & 15;
    const int b   = cta >> 11;
    const int q0  = qb * 16;
    const int tid = threadIdx.x;
    const int wid  = tid >> 5;
    const int lane = tid & 31;

    const float* Qg = g_Q + ((size_t)(b * HH + h) * SS + q0) * HD;
    const float* Kg = g_K + (size_t)(b * HH + h) * HD * SS;   // [d][s]
    const float* Vg = g_V + (size_t)(b * HH + h) * SS * HD;

    if (tid < 256) {
        const int r  = tid >> 4;
        const int c4 = (tid & 15) * 4;
        float4 v = *(const float4*)&Qg[r * HD + c4];
        qt[(c4 + 0) * 16 + r] = v.x;
        qt[(c4 + 1) * 16 + r] = v.y;
        qt[(c4 + 2) * 16 + r] = v.z;
        qt[(c4 + 3) * 16 + r] = v.w;
    }

    // ---- Phase 1: raw = Q K^T (fp32, order-preserving); sc = 1/(8 raw) ----
    const int rg  = tid >> 7;
    const int cg  = tid & 127;
    const int r0  = rg * 4;
    const int cg2 = cg * 2;

    {
        float* buf0 = vbuf;                // [32][256]
        float* buf1 = vbuf + 8192;
        const int lf_d = tid >> 6;
        const int lf_c = (tid & 63) * 4;
        {
            float* db = buf0;
#pragma unroll
            for (int i = 0; i < 4; i++) {
                const int dl = lf_d + i * 8;
                cpasync16(smem_addr(&db[dl * 256 + lf_c]),
                          Kg + (size_t)dl * SS + lf_c);
            }
            CP_COMMIT();
        }

        for (int kc = 0; kc < 8; kc++) {
            u64cu a01c0 = 0ULL, a23c0 = 0ULL, a01c1 = 0ULL, a23c1 = 0ULL;
#pragma unroll
            for (int dh = 0; dh < 2; dh++) {
                const int s = kc * 2 + dh;
                CP_WAIT0();
                __syncthreads();
                if (s < 15) {
                    const int s1  = s + 1;
                    const int kc1 = s1 >> 1, dh1 = s1 & 1;
                    float* db = (s1 & 1) ? buf1 : buf0;
#pragma unroll
                    for (int i = 0; i < 4; i++) {
                        const int dl = lf_d + i * 8;
                        cpasync16(smem_addr(&db[dl * 256 + lf_c]),
                                  Kg + (size_t)(dh1 * 32 + dl) * SS
                                     + kc1 * 256 + lf_c);
                    }
                    CP_COMMIT();
                }
                const float* kb = (s & 1) ? buf1 : buf0;
#pragma unroll 8
                for (int dd = 0; dd < 32; dd++) {
                    const int d = dh * 32 + dd;
                    F4U2 qv;
                    qv.f4 = *(const float4*)&qt[d * 16 + r0];
                    const u64cu q01 = qv.u2[0], q23 = qv.u2[1];
                    float2 kvv = *(const float2*)&kb[dd * 256 + cg2];
                    const u64cu k0d = dup2(kvv.x);
                    const u64cu k1d = dup2(kvv.y);
                    fma2(a01c0, q01, k0d);
                    fma2(a23c0, q23, k0d);
                    fma2(a01c1, q01, k1d);
                    fma2(a23c1, q23, k1d);
                }
            }
            {
                float2 c0lo = up2(a01c0), c0hi = up2(a23c0);
                float2 c1lo = up2(a01c1), c1hi = up2(a23c1);
                float rowv[4][2] = {{c0lo.x, c1lo.x}, {c0lo.y, c1lo.y},
                                    {c0hi.x, c1hi.x}, {c0hi.y, c1hi.y}};
#pragma unroll
                for (int i = 0; i < 4; i++) {
                    float2 sv;
                    sv.x = __fdividef(1.0f, 8.0f * rowv[i][0]);
                    sv.y = __fdividef(1.0f, 8.0f * rowv[i][1]);
                    *(float2*)&sc[(r0 + i) * SC_STR + kc * 256 + cg2] = sv;
                }
            }
        }
    }
    __syncthreads();

    // ---- Phase 2: softmax (store e only) + fused attn_mean ----
    {
        float* row = sc + wid * SC_STR;
        float m = -3.4e38f;
        for (int k = lane; k < 2048; k += 32) m = fmaxf(m, row[k]);
#pragma unroll
        for (int o = 16; o; o >>= 1) m = fmaxf(m, __shfl_xor_sync(0xffffffffu, m, o));
        float ssum = 0.0f;
        for (int k = lane; k < 2048; k += 32) {
            float e = __expf(row[k] - m);
            row[k] = e;
            ssum += e;
        }
#pragma unroll
        for (int o = 16; o; o >>= 1) ssum += __shfl_xor_sync(0xffffffffu, ssum, o);
        const float inv = __fdividef(1.0f, ssum);
        if (lane == 0) sinv[wid] = inv;

        const float invm = inv * 0.0625f;
        float* am = out + (size_t)BB * SS * DD
                  + ((size_t)(b * SS + q0 + wid)) * SS;
        for (int k4 = lane * 4; k4 < 2048; k4 += 128) {
            float4 v = *(const float4*)&row[k4];
            float4 vm = make_float4(v.x * invm, v.y * invm,
                                    v.z * invm, v.w * invm);
            asm volatile("red.global.add.v4.f32 [%0], {%1, %2, %3, %4};"
                         :: "l"(am + k4), "f"(vm.x), "f"(vm.y), "f"(vm.z), "f"(vm.w)
                         : "memory");
        }
    }
    __syncthreads();    // sinv visible to all warps; sc final

    // ---- Phase 3: out += (e*inv) @ V — WARP-PRIVATE pipeline, no barriers --
    {
        const int lr = lane >> 2;
        const int lc = lane & 3;
        const float inv_lo = sinv[lr];
        const float inv_hi = sinv[lr + 8];

        float* pw = vbuf + wid * 1152;     // 2 private buffers of [8][72]

        float c[8][4];
#pragma unroll
        for (int nt = 0; nt < 8; nt++)
#pragma unroll
            for (int e = 0; e < 4; e++) c[nt][e] = 0.0f;

        // prologue: issue slice for step 0 into buffer 0
        {
#pragma unroll
            for (int i = 0; i < 4; i++) {
                const int ch  = lane + i * 32;     // 0..127 chunk id
                const int row = ch >> 4;           // 0..7
                const int seg = (ch & 15) * 4;
                cpasync16(smem_addr(&pw[row * 72 + seg]),
                          Vg + (size_t)(wid * 8 + row) * HD + seg);
            }
            CP_COMMIT();
        }

        for (int s = 0; s < 16; s++) {
            if (s < 15) {
                float* db = pw + ((s + 1) & 1) * 576;
#pragma unroll
                for (int i = 0; i < 4; i++) {
                    const int ch  = lane + i * 32;
                    const int row = ch >> 4;
                    const int seg = (ch & 15) * 4;
                    cpasync16(smem_addr(&db[row * 72 + seg]),
                              Vg + (size_t)((s + 1) * 128 + wid * 8 + row) * HD
                                 + seg);
                }
                CP_COMMIT();
                CP_WAIT1();        // step-s slice complete
            } else {
                CP_WAIT0();
            }
            __syncwarp();
            const float* vb = pw + (s & 1) * 576;

            uint32_t a[4];
            const int ac = s * 128 + wid * 8 + lc;
            a[0] = f2tf32(sc[lr * SC_STR + ac] * inv_lo);
            a[1] = f2tf32(sc[(lr + 8) * SC_STR + ac] * inv_hi);
            a[2] = f2tf32(sc[lr * SC_STR + ac + 4] * inv_lo);
            a[3] = f2tf32(sc[(lr + 8) * SC_STR + ac + 4] * inv_hi);
#pragma unroll
            for (int nt = 0; nt < 8; nt++) {
                uint32_t bf[2];
                const int n = nt * 8 + lr;
                bf[0] = __float_as_uint(vb[lc * 72 + n]);          // pre-tf32
                bf[1] = __float_as_uint(vb[(lc + 4) * 72 + n]);
                mma8(c[nt], a, bf);
            }
        }

        float* ob = out + ((size_t)(b * SS + q0)) * DD + h * HD;
#pragma unroll
        for (int nt = 0; nt < 8; nt++) {
            const int col = nt * 8 + 2 * lc;
            float* p0 = ob + (size_t)lr * DD + col;
            float* p1 = ob + (size_t)(lr + 8) * DD + col;
            asm volatile("red.global.add.v2.f32 [%0], {%1, %2};"
                         :: "l"(p0), "f"(c[nt][0]), "f"(c[nt][1]) : "memory");
            asm volatile("red.global.add.v2.f32 [%0], {%1, %2};"
                         :: "l"(p1), "f"(c[nt][2]), "f"(c[nt][3]) : "memory");
        }
    }
}

// ---------------------------------------------------------------------------
extern "C" void kernel_launch(void* const* d_in, const int* in_sizes, int n_in,
                              void* d_out, int out_size)
{
    const float* query = (const float*)d_in[0];
    const float* key_  = (const float*)d_in[1];
    const float* value = (const float*)d_in[2];
    const float* Wq    = (const float*)d_in[3];
    const float* bq    = (const float*)d_in[4];
    const float* Wk    = (const float*)d_in[5];
    const float* bk    = (const float*)d_in[6];
    const float* Wv    = (const float*)d_in[7];
    const float* bv    = (const float*)d_in[8];
    float* out = (float*)d_out;

    cudaMemsetAsync(out, 0,
                    (size_t)(BB * SS * DD + (size_t)BB * SS * SS) * sizeof(float));

    cudaFuncSetAttribute(proj_all,
                         cudaFuncAttributeMaxDynamicSharedMemorySize, PROJ_SMEM);
    dim3 pg(DD / 128, (BB * SS) / 128, 3);
    proj_all<<<pg, 256, PROJ_SMEM>>>(query, key_, value, Wq, Wk, Wv, bq, bk, bv);

    cudaFuncSetAttribute(attn_kernel,
                         cudaFuncAttributeMaxDynamicSharedMemorySize, SMEM_BYTES);
    attn_kernel<<<BB * HH * (SS / 16), 512, SMEM_BYTES>>>(out);
}